// round 3
// baseline (speedup 1.0000x reference)
#include <cuda_runtime.h>
#include <cuda_bf16.h>

#define NDIM 384
#define NN   (NDIM * NDIM)   // 147456
#define DDIM 128

// ---- scratch (device globals; no allocation allowed) ----
__device__ __nv_bfloat16 g_left [(size_t)DDIM * NN];   // [d][i*N+k] bf16
__device__ __nv_bfloat16 g_right[(size_t)DDIM * NN];   // [d][j*N+k] bf16
__device__ float         g_outgate[(size_t)NN * DDIM]; // [pos][h] fp32
__device__ __nv_bfloat16 g_accbf[(size_t)DDIM * NN];   // [d][i*N+j] bf16 (einsum out, rounded like ref)

__device__ __forceinline__ float sigf(float v) { return 1.f / (1.f + __expf(-v)); }

// =====================================================================
// Kernel A: LayerNorm + 5 projections + gating, 64 rows per block
// =====================================================================
struct SmemA {
    float ysT[128][68];          // k-major normalized x (pad 68: aligned, low-conflict)
    float wsT[128][132];         // k-major weight tile  (pad 132)
    __nv_bfloat16 obf[64][130];  // output transpose staging (pad 130)
    float mrow[64];
    float nw[128];
    float nb[128];
};

__device__ __forceinline__ void stageW(SmemA& sm, const float* __restrict__ W, int tid) {
    #pragma unroll
    for (int t = 0; t < 32; t++) {
        int idx = tid + t * 512;
        int h = idx >> 7, k = idx & 127;
        sm.wsT[k][h] = W[idx];          // W is [H][D] row-major
    }
}

__device__ __forceinline__ void gemmA(const SmemA& sm, float acc[4][4], int r0, int c0) {
    #pragma unroll
    for (int i = 0; i < 4; i++)
        #pragma unroll
        for (int j = 0; j < 4; j++) acc[i][j] = 0.f;
    #pragma unroll 4
    for (int k = 0; k < 128; k++) {
        float a[4], b[4];
        *(float4*)a = *(const float4*)&sm.ysT[k][r0];
        *(float4*)b = *(const float4*)&sm.wsT[k][c0];
        #pragma unroll
        for (int i = 0; i < 4; i++)
            #pragma unroll
            for (int j = 0; j < 4; j++) acc[i][j] += a[i] * b[j];
    }
}

__device__ __forceinline__ void combineStore(SmemA& sm, const float accV[4][4],
                                             const float accG[4][4], int r0, int c0) {
    #pragma unroll
    for (int i = 0; i < 4; i++) {
        float m = sm.mrow[r0 + i];
        #pragma unroll
        for (int j = 0; j < 4; j++) {
            float v = accV[i][j] * m * sigf(accG[i][j]);
            sm.obf[r0 + i][c0 + j] = __float2bfloat16(v);
        }
    }
}

__device__ __forceinline__ void flushT(SmemA& sm, __nv_bfloat16* dst, int pos0, int tid) {
    #pragma unroll
    for (int t = 0; t < 16; t++) {
        int idx = tid + t * 512;
        int dch = idx >> 6, p = idx & 63;
        dst[(size_t)dch * NN + pos0 + p] = sm.obf[p][dch];
    }
}

__global__ void __launch_bounds__(512, 1)
kernA(const float* __restrict__ x, const float* __restrict__ mask,
      const float* __restrict__ nw, const float* __restrict__ nb,
      const float* __restrict__ Wl, const float* __restrict__ Wlg,
      const float* __restrict__ Wr, const float* __restrict__ Wrg,
      const float* __restrict__ Wog)
{
    extern __shared__ char raw[];
    SmemA& sm = *reinterpret_cast<SmemA*>(raw);
    const int tid = threadIdx.x;
    const int pos0 = blockIdx.x * 64;

    if (tid < 128) { sm.nw[tid] = nw[tid]; sm.nb[tid] = nb[tid]; }
    if (tid < 64)  sm.mrow[tid] = mask[pos0 + tid];
    __syncthreads();

    const int wid = tid >> 5, lid = tid & 31;
    // LayerNorm: 16 warps x 4 rows each, write k-major normalized values
    #pragma unroll
    for (int rr = 0; rr < 4; rr++) {
        int r = wid * 4 + rr;
        const float* xr = x + (size_t)(pos0 + r) * 128;
        float v[4]; float s = 0.f, q = 0.f;
        #pragma unroll
        for (int t = 0; t < 4; t++) { v[t] = xr[lid + 32 * t]; s += v[t]; q += v[t] * v[t]; }
        #pragma unroll
        for (int o = 16; o; o >>= 1) {
            s += __shfl_xor_sync(0xffffffffu, s, o);
            q += __shfl_xor_sync(0xffffffffu, q, o);
        }
        float mu = s * (1.f / 128.f);
        float rstd = rsqrtf(q * (1.f / 128.f) - mu * mu + 1e-5f);
        #pragma unroll
        for (int t = 0; t < 4; t++) {
            int k = lid + 32 * t;
            sm.ysT[k][r] = (v[t] - mu) * rstd * sm.nw[k] + sm.nb[k];
        }
    }
    __syncthreads();

    const int r0 = (tid >> 5) * 4;   // row group 0..60
    const int c0 = (tid & 31) * 4;   // col group 0..124
    float accV[4][4], accG[4][4];

    // ---- left = LN(x)@Wl^T * mask * sigmoid(LN(x)@Wlg^T) ----
    stageW(sm, Wl, tid);  __syncthreads();
    gemmA(sm, accV, r0, c0); __syncthreads();
    stageW(sm, Wlg, tid); __syncthreads();
    gemmA(sm, accG, r0, c0);
    combineStore(sm, accV, accG, r0, c0); __syncthreads();
    flushT(sm, g_left, pos0, tid); __syncthreads();

    // ---- right ----
    stageW(sm, Wr, tid);  __syncthreads();
    gemmA(sm, accV, r0, c0); __syncthreads();
    stageW(sm, Wrg, tid); __syncthreads();
    gemmA(sm, accG, r0, c0);
    combineStore(sm, accV, accG, r0, c0); __syncthreads();
    flushT(sm, g_right, pos0, tid); __syncthreads();

    // ---- out_gate = sigmoid(LN(x)@Wog^T), stored [pos][h] ----
    stageW(sm, Wog, tid); __syncthreads();
    gemmA(sm, accV, r0, c0);
    #pragma unroll
    for (int i = 0; i < 4; i++) {
        float4 o;
        o.x = sigf(accV[i][0]); o.y = sigf(accV[i][1]);
        o.z = sigf(accV[i][2]); o.w = sigf(accV[i][3]);
        *(float4*)(g_outgate + (size_t)(pos0 + r0 + i) * 128 + c0) = o;
    }
}

// =====================================================================
// Kernel B: per-channel batched GEMM  acc_d = L_d (384x384) @ R_d^T
// grid (6, 6, 128), 256 threads, 64x64 tile, k-tile 32
// Result rounded to bf16 (reference's einsum output dtype is bf16).
// =====================================================================
__global__ void __launch_bounds__(256) kernB()
{
    __shared__ float As[32][68];
    __shared__ float Bs[32][68];
    const int tid = threadIdx.x;
    const int d  = blockIdx.z;
    const int i0 = blockIdx.y * 64;
    const int j0 = blockIdx.x * 64;
    const __nv_bfloat16* A = g_left  + (size_t)d * NN;
    const __nv_bfloat16* B = g_right + (size_t)d * NN;

    float acc[4][4] = {};
    const int tx = tid & 15, ty = tid >> 4;

    for (int kb = 0; kb < NDIM; kb += 32) {
        #pragma unroll
        for (int t = 0; t < 4; t++) {
            int idx = tid + t * 256;
            int r = idx >> 4, c2 = (idx & 15) * 2;
            float2 fa = __bfloat1622float2(
                *(const __nv_bfloat162*)(A + (size_t)(i0 + r) * NDIM + kb + c2));
            As[c2][r] = fa.x; As[c2 + 1][r] = fa.y;
            float2 fb = __bfloat1622float2(
                *(const __nv_bfloat162*)(B + (size_t)(j0 + r) * NDIM + kb + c2));
            Bs[c2][r] = fb.x; Bs[c2 + 1][r] = fb.y;
        }
        __syncthreads();
        #pragma unroll
        for (int k = 0; k < 32; k++) {
            float a[4], b[4];
            *(float4*)a = *(const float4*)&As[k][ty * 4];
            *(float4*)b = *(const float4*)&Bs[k][tx * 4];
            #pragma unroll
            for (int i = 0; i < 4; i++)
                #pragma unroll
                for (int j = 0; j < 4; j++) acc[i][j] += a[i] * b[j];
        }
        __syncthreads();
    }

    __nv_bfloat16* C = g_accbf + (size_t)d * NN;
    #pragma unroll
    for (int i = 0; i < 4; i++) {
        __nv_bfloat162 o01 = make_bfloat162(__float2bfloat16(acc[i][0]), __float2bfloat16(acc[i][1]));
        __nv_bfloat162 o23 = make_bfloat162(__float2bfloat16(acc[i][2]), __float2bfloat16(acc[i][3]));
        __nv_bfloat162* dst = (__nv_bfloat162*)(C + (size_t)(i0 + ty * 4 + i) * NDIM + j0 + tx * 4);
        dst[0] = o01; dst[1] = o23;
    }
}

// =====================================================================
// Kernel C: out-LN over H + out_gate + @W_out^T, 64 positions per block
// =====================================================================
struct SmemC {
    float s[64][133];      // [pos][h], pad 133 -> conflict-free transpose writes
    float WoT[128][132];   // [h][dd]
    float onw[128];
    float onb[128];
};

__global__ void __launch_bounds__(512, 1)
kernC(const float* __restrict__ onw, const float* __restrict__ onb,
      const float* __restrict__ Wout, float* __restrict__ out)
{
    extern __shared__ char raw[];
    SmemC& sm = *reinterpret_cast<SmemC*>(raw);
    const int tid = threadIdx.x;
    const int pos0 = blockIdx.x * 64;

    if (tid < 128) { sm.onw[tid] = onw[tid]; sm.onb[tid] = onb[tid]; }
    #pragma unroll
    for (int t = 0; t < 32; t++) {           // W_out is [D][H] row-major
        int idx = tid + t * 512;
        int dd = idx >> 7, h = idx & 127;
        sm.WoT[h][dd] = Wout[idx];
    }
    #pragma unroll
    for (int t = 0; t < 16; t++) {           // gather 128 d-planes -> [pos][h] tile
        int idx = tid + t * 512;
        int dch = idx >> 6, p = idx & 63;
        sm.s[p][dch] = __bfloat162float(g_accbf[(size_t)dch * NN + pos0 + p]);
    }
    __syncthreads();

    const int wid = tid >> 5, lid = tid & 31;
    #pragma unroll
    for (int pp = 0; pp < 4; pp++) {
        int p = wid * 4 + pp;
        float v[4]; float ssum = 0.f, q = 0.f;
        #pragma unroll
        for (int t = 0; t < 4; t++) {
            v[t] = sm.s[p][lid + 32 * t];
            ssum += v[t]; q += v[t] * v[t];
        }
        #pragma unroll
        for (int o = 16; o; o >>= 1) {
            ssum += __shfl_xor_sync(0xffffffffu, ssum, o);
            q    += __shfl_xor_sync(0xffffffffu, q, o);
        }
        float mu = ssum * (1.f / 128.f);
        float rstd = rsqrtf(q * (1.f / 128.f) - mu * mu + 1e-5f);
        const float* og = g_outgate + (size_t)(pos0 + p) * 128;
        #pragma unroll
        for (int t = 0; t < 4; t++) {
            int h = lid + 32 * t;
            float g = ((v[t] - mu) * rstd * sm.onw[h] + sm.onb[h]) * og[h];
            sm.s[p][h] = g;
        }
        __syncwarp();
        float4 a = make_float4(0.f, 0.f, 0.f, 0.f);
        #pragma unroll 8
        for (int h = 0; h < 128; h++) {
            float gs = sm.s[p][h];
            float4 w = *(const float4*)&sm.WoT[h][lid * 4];
            a.x += gs * w.x; a.y += gs * w.y; a.z += gs * w.z; a.w += gs * w.w;
        }
        *(float4*)(out + (size_t)(pos0 + p) * 128 + lid * 4) = a;
        __syncwarp();
    }
}

// =====================================================================
extern "C" void kernel_launch(void* const* d_in, const int* in_sizes, int n_in,
                              void* d_out, int out_size)
{
    (void)in_sizes; (void)n_in; (void)out_size;
    const float* x    = (const float*)d_in[0];
    const float* mask = (const float*)d_in[1];
    const float* nw   = (const float*)d_in[2];
    const float* nb   = (const float*)d_in[3];
    const float* Wl   = (const float*)d_in[4];
    const float* Wr   = (const float*)d_in[5];
    const float* Wlg  = (const float*)d_in[6];
    const float* Wrg  = (const float*)d_in[7];
    const float* Wog  = (const float*)d_in[8];
    const float* onw  = (const float*)d_in[9];
    const float* onb  = (const float*)d_in[10];
    const float* Wout = (const float*)d_in[11];
    float* out = (float*)d_out;

    cudaFuncSetAttribute(kernA, cudaFuncAttributeMaxDynamicSharedMemorySize, (int)sizeof(SmemA));
    cudaFuncSetAttribute(kernC, cudaFuncAttributeMaxDynamicSharedMemorySize, (int)sizeof(SmemC));

    kernA<<<NN / 64, 512, sizeof(SmemA)>>>(x, mask, nw, nb, Wl, Wlg, Wr, Wrg, Wog);
    kernB<<<dim3(6, 6, 128), 256>>>();
    kernC<<<NN / 64, 512, sizeof(SmemC)>>>(onw, onb, Wout, out);
}

// round 6
// speedup vs baseline: 1.4920x; 1.4920x over previous
#include <cuda_runtime.h>
#include <cuda_bf16.h>
#include <cstdint>

#define NDIM 384
#define NN   (NDIM * NDIM)   // 147456
#define DDIM 128

// ---- scratch (device globals; no allocation allowed) ----
__device__ __nv_bfloat16 g_left [(size_t)DDIM * NN];   // [d][i*N+k] bf16
__device__ __nv_bfloat16 g_right[(size_t)DDIM * NN];   // [d][j*N+k] bf16
__device__ float         g_outgate[(size_t)NN * DDIM]; // [pos][h] fp32
__device__ __nv_bfloat16 g_accbf[(size_t)DDIM * NN];   // [d][i*N+j] bf16 (einsum out)

__device__ __forceinline__ float sigf(float v) { return 1.f / (1.f + __expf(-v)); }

// =====================================================================
// Kernel A: LayerNorm + 5 projections + gating
// 256 threads, 64 rows/block, 8x4 register tile, 2 CTAs/SM
// =====================================================================
struct SmemA {
    float ysT[128][68];              // k-major normalized x
    union {
        float wsT[128][132];         // k-major weight tile
        __nv_bfloat16 obf[64][130];  // output transpose staging (aliases wsT)
    };
    float mrow[64];
    float nw[128];
    float nb[128];
};

__device__ __forceinline__ void stageW(SmemA& sm, const float* __restrict__ W, int tid) {
    #pragma unroll
    for (int t = 0; t < 64; t++) {
        int idx = tid + t * 256;
        int h = idx >> 7, k = idx & 127;
        sm.wsT[k][h] = W[idx];          // W is [H][D] row-major
    }
}

__device__ __forceinline__ void gemmA(const SmemA& sm, float acc[8][4], int r0, int c0) {
    #pragma unroll
    for (int i = 0; i < 8; i++)
        #pragma unroll
        for (int j = 0; j < 4; j++) acc[i][j] = 0.f;
    #pragma unroll 4
    for (int k = 0; k < 128; k++) {
        float a[8], b[4];
        *(float4*)&a[0] = *(const float4*)&sm.ysT[k][r0];      // warp broadcast
        *(float4*)&a[4] = *(const float4*)&sm.ysT[k][r0 + 4];  // warp broadcast
        *(float4*)b = *(const float4*)&sm.wsT[k][c0];
        #pragma unroll
        for (int i = 0; i < 8; i++)
            #pragma unroll
            for (int j = 0; j < 4; j++) acc[i][j] += a[i] * b[j];
    }
}

__global__ void __launch_bounds__(256, 2)
kernA(const float* __restrict__ x, const float* __restrict__ mask,
      const float* __restrict__ nw, const float* __restrict__ nb,
      const float* __restrict__ Wl, const float* __restrict__ Wlg,
      const float* __restrict__ Wr, const float* __restrict__ Wrg,
      const float* __restrict__ Wog)
{
    extern __shared__ char raw[];
    SmemA& sm = *reinterpret_cast<SmemA*>(raw);
    const int tid = threadIdx.x;
    const int pos0 = blockIdx.x * 64;
    const int wid = tid >> 5, lid = tid & 31;

    if (tid < 128) { sm.nw[tid] = nw[tid]; sm.nb[tid] = nb[tid]; }
    if (tid < 64)  sm.mrow[tid] = mask[pos0 + tid];
    __syncthreads();

    // LayerNorm: 8 warps x 8 rows each, write k-major normalized values
    #pragma unroll
    for (int rr = 0; rr < 8; rr++) {
        int r = wid * 8 + rr;
        const float* xr = x + (size_t)(pos0 + r) * 128;
        float v[4]; float s = 0.f, q = 0.f;
        #pragma unroll
        for (int t = 0; t < 4; t++) { v[t] = xr[lid + 32 * t]; s += v[t]; q += v[t] * v[t]; }
        #pragma unroll
        for (int o = 16; o; o >>= 1) {
            s += __shfl_xor_sync(0xffffffffu, s, o);
            q += __shfl_xor_sync(0xffffffffu, q, o);
        }
        float mu = s * (1.f / 128.f);
        float rstd = rsqrtf(q * (1.f / 128.f) - mu * mu + 1e-5f);
        #pragma unroll
        for (int t = 0; t < 4; t++) {
            int k = lid + 32 * t;
            sm.ysT[k][r] = (v[t] - mu) * rstd * sm.nw[k] + sm.nb[k];
        }
    }
    __syncthreads();

    const int r0 = wid * 8;          // row group 0..56
    const int c0 = lid * 4;          // col group 0..124
    float accV[8][4], accG[8][4];

    #pragma unroll 1
    for (int side = 0; side < 2; side++) {
        const float* Wv = side ? Wr  : Wl;
        const float* Wg = side ? Wrg : Wlg;
        __nv_bfloat16* dst = side ? g_right : g_left;

        stageW(sm, Wv, tid); __syncthreads();
        gemmA(sm, accV, r0, c0); __syncthreads();
        stageW(sm, Wg, tid); __syncthreads();
        gemmA(sm, accG, r0, c0);
        __syncthreads();                       // all wsT reads done (obf aliases wsT)
        #pragma unroll
        for (int i = 0; i < 8; i++) {
            float m = sm.mrow[r0 + i];
            #pragma unroll
            for (int j = 0; j < 4; j++)
                sm.obf[r0 + i][c0 + j] = __float2bfloat16(accV[i][j] * m * sigf(accG[i][j]));
        }
        __syncthreads();
        #pragma unroll
        for (int t = 0; t < 32; t++) {         // transpose flush: [d][pos] planes
            int idx = tid + t * 256;
            int dch = idx >> 6, p = idx & 63;
            dst[(size_t)dch * NN + pos0 + p] = sm.obf[p][dch];
        }
        __syncthreads();
    }

    // ---- out_gate = sigmoid(LN(x)@Wog^T), stored [pos][h] ----
    stageW(sm, Wog, tid); __syncthreads();
    gemmA(sm, accV, r0, c0);
    #pragma unroll
    for (int i = 0; i < 8; i++) {
        float4 o;
        o.x = sigf(accV[i][0]); o.y = sigf(accV[i][1]);
        o.z = sigf(accV[i][2]); o.w = sigf(accV[i][3]);
        *(float4*)(g_outgate + (size_t)(pos0 + r0 + i) * 128 + c0) = o;
    }
}

// =====================================================================
// Kernel B: per-channel batched GEMM  acc_d = L_d (384x384) @ R_d^T
// bf16 HMMA (mma.sync.m16n8k16), 128x128 block tile, 64x32 warp tile
// grid (3, 3, 128), 256 threads
// =====================================================================
__device__ __forceinline__ void ldm4(uint32_t (&r)[4], uint32_t saddr) {
    asm volatile("ldmatrix.sync.aligned.m8n8.x4.shared.b16 {%0,%1,%2,%3}, [%4];"
        : "=r"(r[0]), "=r"(r[1]), "=r"(r[2]), "=r"(r[3]) : "r"(saddr));
}
__device__ __forceinline__ void mma16816(float (&d)[4], const uint32_t (&a)[4],
                                         uint32_t b0, uint32_t b1) {
    asm volatile("mma.sync.aligned.m16n8k16.row.col.f32.bf16.bf16.f32 "
        "{%0,%1,%2,%3}, {%4,%5,%6,%7}, {%8,%9}, {%0,%1,%2,%3};"
        : "+f"(d[0]), "+f"(d[1]), "+f"(d[2]), "+f"(d[3])
        : "r"(a[0]), "r"(a[1]), "r"(a[2]), "r"(a[3]), "r"(b0), "r"(b1));
}

// swizzled smem offset (elements) for tile[row][chunk*8..chunk*8+7], 16B chunks
__device__ __forceinline__ uint32_t swOff(int row, int chunk) {
    return (uint32_t)(row * 64 + ((chunk ^ (row & 7)) << 3));
}

__global__ void __launch_bounds__(256) kernB()
{
    __shared__ __nv_bfloat16 As[128 * 64];
    __shared__ __nv_bfloat16 Bs[128 * 64];
    const int tid = threadIdx.x;
    const int d  = blockIdx.z;
    const int i0 = blockIdx.y * 128;
    const int j0 = blockIdx.x * 128;
    const __nv_bfloat16* A = g_left  + (size_t)d * NN;
    const __nv_bfloat16* B = g_right + (size_t)d * NN;

    const int warp = tid >> 5, lane = tid & 31;
    const int m0 = (warp >> 2) * 64;       // 2 warp-rows
    const int n0 = (warp & 3) * 32;        // 4 warp-cols

    const uint32_t baseA = (uint32_t)__cvta_generic_to_shared(As);
    const uint32_t baseB = (uint32_t)__cvta_generic_to_shared(Bs);

    float acc[4][4][4];
    #pragma unroll
    for (int mi = 0; mi < 4; mi++)
        #pragma unroll
        for (int ni = 0; ni < 4; ni++)
            #pragma unroll
            for (int e = 0; e < 4; e++) acc[mi][ni][e] = 0.f;

    // precompute per-lane ldmatrix row/col pieces
    const int aRow = ((lane & 8) ? 8 : 0) + (lane & 7);  // + m0 + mi*16
    const int aChk = (lane >> 4);                        // + kk/8
    const int bRow = ((lane & 16) ? 8 : 0) + (lane & 7); // + n0 + p*16
    const int bChk = ((lane >> 3) & 1);                  // + kk/8

    for (int kb = 0; kb < NDIM; kb += 64) {
        __syncthreads();
        #pragma unroll
        for (int t = 0; t < 4; t++) {
            int idx = tid + t * 256;
            int r = idx >> 3, c = idx & 7;
            uint32_t so = swOff(r, c);
            *(uint4*)(As + so) = *(const uint4*)(A + (size_t)(i0 + r) * NDIM + kb + c * 8);
            *(uint4*)(Bs + so) = *(const uint4*)(B + (size_t)(j0 + r) * NDIM + kb + c * 8);
        }
        __syncthreads();

        #pragma unroll
        for (int kk = 0; kk < 64; kk += 16) {
            uint32_t af[4][4];
            #pragma unroll
            for (int mi = 0; mi < 4; mi++) {
                int row = m0 + mi * 16 + aRow;
                ldm4(af[mi], baseA + swOff(row, (kk >> 3) + aChk) * 2);
            }
            uint32_t bf[2][4];   // each covers two n8 tiles
            #pragma unroll
            for (int p = 0; p < 2; p++) {
                int row = n0 + p * 16 + bRow;
                ldm4(bf[p], baseB + swOff(row, (kk >> 3) + bChk) * 2);
            }
            #pragma unroll
            for (int mi = 0; mi < 4; mi++) {
                mma16816(acc[mi][0], af[mi], bf[0][0], bf[0][1]);
                mma16816(acc[mi][1], af[mi], bf[0][2], bf[0][3]);
                mma16816(acc[mi][2], af[mi], bf[1][0], bf[1][1]);
                mma16816(acc[mi][3], af[mi], bf[1][2], bf[1][3]);
            }
        }
    }

    __nv_bfloat16* C = g_accbf + (size_t)d * NN;
    const int r = lane >> 2, cp = (lane & 3) * 2;
    #pragma unroll
    for (int mi = 0; mi < 4; mi++)
        #pragma unroll
        for (int ni = 0; ni < 4; ni++) {
            int gi = i0 + m0 + mi * 16 + r;
            int gj = j0 + n0 + ni * 8 + cp;
            *(__nv_bfloat162*)(C + (size_t)gi * NDIM + gj) =
                __floats2bfloat162_rn(acc[mi][ni][0], acc[mi][ni][1]);
            *(__nv_bfloat162*)(C + (size_t)(gi + 8) * NDIM + gj) =
                __floats2bfloat162_rn(acc[mi][ni][2], acc[mi][ni][3]);
        }
}

// =====================================================================
// Kernel C: out-LN over H + out_gate + @W_out^T, 64 positions per block
// =====================================================================
struct SmemC {
    float s[64][132];      // [pos][h]
    float WoT[128][132];   // [h][dd]
    float onw[128];
    float onb[128];
};

__global__ void __launch_bounds__(512, 2)
kernC(const float* __restrict__ onw, const float* __restrict__ onb,
      const float* __restrict__ Wout, float* __restrict__ out)
{
    extern __shared__ char raw[];
    SmemC& sm = *reinterpret_cast<SmemC*>(raw);
    const int tid = threadIdx.x;
    const int pos0 = blockIdx.x * 64;

    if (tid < 128) { sm.onw[tid] = onw[tid]; sm.onb[tid] = onb[tid]; }
    #pragma unroll
    for (int t = 0; t < 32; t++) {           // W_out is [D][H] row-major
        int idx = tid + t * 512;
        int dd = idx >> 7, h = idx & 127;
        sm.WoT[h][dd] = Wout[idx];
    }
    #pragma unroll
    for (int t = 0; t < 16; t++) {           // gather 128 d-planes -> [pos][h] tile
        int idx = tid + t * 512;
        int dch = idx >> 6, p = idx & 63;
        sm.s[p][dch] = __bfloat162float(g_accbf[(size_t)dch * NN + pos0 + p]);
    }
    __syncthreads();

    const int wid = tid >> 5, lid = tid & 31;
    #pragma unroll
    for (int pp = 0; pp < 4; pp++) {
        int p = wid * 4 + pp;
        float v[4]; float ssum = 0.f, q = 0.f;
        #pragma unroll
        for (int t = 0; t < 4; t++) {
            v[t] = sm.s[p][lid + 32 * t];
            ssum += v[t]; q += v[t] * v[t];
        }
        #pragma unroll
        for (int o = 16; o; o >>= 1) {
            ssum += __shfl_xor_sync(0xffffffffu, ssum, o);
            q    += __shfl_xor_sync(0xffffffffu, q, o);
        }
        float mu = ssum * (1.f / 128.f);
        float rstd = rsqrtf(q * (1.f / 128.f) - mu * mu + 1e-5f);
        const float* og = g_outgate + (size_t)(pos0 + p) * 128;
        #pragma unroll
        for (int t = 0; t < 4; t++) {
            int h = lid + 32 * t;
            float g = ((v[t] - mu) * rstd * sm.onw[h] + sm.onb[h]) * og[h];
            sm.s[p][h] = g;
        }
        __syncwarp();
        float4 a = make_float4(0.f, 0.f, 0.f, 0.f);
        #pragma unroll 8
        for (int h = 0; h < 128; h++) {
            float gs = sm.s[p][h];
            float4 w = *(const float4*)&sm.WoT[h][lid * 4];
            a.x += gs * w.x; a.y += gs * w.y; a.z += gs * w.z; a.w += gs * w.w;
        }
        *(float4*)(out + (size_t)(pos0 + p) * 128 + lid * 4) = a;
        __syncwarp();
    }
}

// =====================================================================
extern "C" void kernel_launch(void* const* d_in, const int* in_sizes, int n_in,
                              void* d_out, int out_size)
{
    (void)in_sizes; (void)n_in; (void)out_size;
    const float* x    = (const float*)d_in[0];
    const float* mask = (const float*)d_in[1];
    const float* nw   = (const float*)d_in[2];
    const float* nb   = (const float*)d_in[3];
    const float* Wl   = (const float*)d_in[4];
    const float* Wr   = (const float*)d_in[5];
    const float* Wlg  = (const float*)d_in[6];
    const float* Wrg  = (const float*)d_in[7];
    const float* Wog  = (const float*)d_in[8];
    const float* onw  = (const float*)d_in[9];
    const float* onb  = (const float*)d_in[10];
    const float* Wout = (const float*)d_in[11];
    float* out = (float*)d_out;

    cudaFuncSetAttribute(kernA, cudaFuncAttributeMaxDynamicSharedMemorySize, (int)sizeof(SmemA));
    cudaFuncSetAttribute(kernC, cudaFuncAttributeMaxDynamicSharedMemorySize, (int)sizeof(SmemC));

    kernA<<<NN / 64, 256, sizeof(SmemA)>>>(x, mask, nw, nb, Wl, Wlg, Wr, Wrg, Wog);
    kernB<<<dim3(3, 3, 128), 256>>>();
    kernC<<<NN / 64, 512, sizeof(SmemC)>>>(onw, onb, Wout, out);
}

// round 8
// speedup vs baseline: 2.3297x; 1.5615x over previous
#include <cuda_runtime.h>
#include <cuda_bf16.h>
#include <cstdint>

#define NDIM 384
#define NN   (NDIM * NDIM)   // 147456
#define DDIM 128

// ---- scratch (device globals; no allocation allowed) ----
__device__ __nv_bfloat16 g_left [(size_t)DDIM * NN];   // [d][i*N+k] bf16
__device__ __nv_bfloat16 g_right[(size_t)DDIM * NN];   // [d][j*N+k] bf16
__device__ float         g_outgate[(size_t)NN * DDIM]; // [pos][h] fp32
__device__ __nv_bfloat16 g_accbf[(size_t)DDIM * NN];   // [d][i*N+j] bf16 (einsum out)

__device__ __forceinline__ float sigf(float v) { return 1.f / (1.f + __expf(-v)); }

// ---- shared mma helpers (validated in kernB since R6) ----
__device__ __forceinline__ void ldm4(uint32_t (&r)[4], uint32_t saddr) {
    asm volatile("ldmatrix.sync.aligned.m8n8.x4.shared.b16 {%0,%1,%2,%3}, [%4];"
        : "=r"(r[0]), "=r"(r[1]), "=r"(r[2]), "=r"(r[3]) : "r"(saddr));
}
__device__ __forceinline__ void mma16816(float (&d)[4], const uint32_t (&a)[4],
                                         uint32_t b0, uint32_t b1) {
    asm volatile("mma.sync.aligned.m16n8k16.row.col.f32.bf16.bf16.f32 "
        "{%0,%1,%2,%3}, {%4,%5,%6,%7}, {%8,%9}, {%0,%1,%2,%3};"
        : "+f"(d[0]), "+f"(d[1]), "+f"(d[2]), "+f"(d[3])
        : "r"(a[0]), "r"(a[1]), "r"(a[2]), "r"(a[3]), "r"(b0), "r"(b1));
}

// =====================================================================
// Kernel A: LayerNorm + 5 projections + gating — bf16x3 split HMMA
// 256 threads, 64 rows/block, block tile 64x128, warp tile 32x32
// x = xh + xl, W = wh + wl (bf16 each); y@W^T ≈ xh wh + xh wl + xl wh
// =====================================================================

// 128-col swizzled offset (elements): row*128 + ((chunk ^ (row&7))<<3), chunk=col>>3
__device__ __forceinline__ uint32_t sw128(int row, int chunk) {
    return (uint32_t)(row * 128 + (((chunk & 7) ^ (row & 7)) << 3) + ((chunk & 8) << 3));
}

struct SmemA4 {
    __nv_bfloat16 xh[64 * 128];          // 16 KB
    __nv_bfloat16 xl[64 * 128];          // 16 KB
    union {
        __nv_bfloat16 wh[128 * 128];     // 32 KB
        __nv_bfloat16 obf[64][130];      // 16.6 KB (aliases wh)
    };
    __nv_bfloat16 wl[128 * 128];         // 32 KB
    float mrow[64];
    float nw[128];
    float nb[128];
};

// stage W[H=128][D=128] row-major -> (wh, wl) swizzled [n][k] tiles
__device__ __forceinline__ void stageW4(SmemA4& sm, const float* __restrict__ W, int tid) {
    #pragma unroll
    for (int t = 0; t < 16; t++) {
        int idx = tid + t * 256;            // float4 index
        int h = idx >> 5, kq = idx & 31;    // kq: which float4 in the row
        float4 w = *(const float4*)(W + h * 128 + kq * 4);
        __nv_bfloat162 h01 = __floats2bfloat162_rn(w.x, w.y);
        __nv_bfloat162 h23 = __floats2bfloat162_rn(w.z, w.w);
        __nv_bfloat162 l01 = __floats2bfloat162_rn(w.x - __bfloat162float(h01.x),
                                                   w.y - __bfloat162float(h01.y));
        __nv_bfloat162 l23 = __floats2bfloat162_rn(w.z - __bfloat162float(h23.x),
                                                   w.w - __bfloat162float(h23.y));
        uint32_t off = sw128(h, kq >> 1) + ((kq & 1) << 2);
        *(__nv_bfloat162*)(sm.wh + off)     = h01;
        *(__nv_bfloat162*)(sm.wh + off + 2) = h23;
        *(__nv_bfloat162*)(sm.wl + off)     = l01;
        *(__nv_bfloat162*)(sm.wl + off + 2) = l23;
    }
}

// 3-pass split gemm: acc[2][4][4] for this warp's 32x32 tile
__device__ __forceinline__ void gemm3(const SmemA4& sm, float acc[2][4][4],
                                      int m0w, int n0w, int lane,
                                      uint32_t bxh, uint32_t bxl,
                                      uint32_t bwh, uint32_t bwl) {
    #pragma unroll
    for (int mi = 0; mi < 2; mi++)
        #pragma unroll
        for (int ni = 0; ni < 4; ni++)
            #pragma unroll
            for (int e = 0; e < 4; e++) acc[mi][ni][e] = 0.f;

    const int aRow = ((lane & 8) ? 8 : 0) + (lane & 7);
    const int aChk = (lane >> 4);
    const int bRow = ((lane & 16) ? 8 : 0) + (lane & 7);
    const int bChk = (lane >> 3) & 1;

    #pragma unroll
    for (int ks = 0; ks < 8; ks++) {           // k16 steps over K=128
        uint32_t ah[2][4], al[2][4], bh[2][4], bl[2][4];
        #pragma unroll
        for (int mi = 0; mi < 2; mi++) {
            uint32_t off = sw128(m0w + mi * 16 + aRow, ks * 2 + aChk) * 2;
            ldm4(ah[mi], bxh + off);
            ldm4(al[mi], bxl + off);
        }
        #pragma unroll
        for (int p = 0; p < 2; p++) {
            uint32_t off = sw128(n0w + p * 16 + bRow, ks * 2 + bChk) * 2;
            ldm4(bh[p], bwh + off);
            ldm4(bl[p], bwl + off);
        }
        #pragma unroll
        for (int mi = 0; mi < 2; mi++) {
            // hi*hi
            mma16816(acc[mi][0], ah[mi], bh[0][0], bh[0][1]);
            mma16816(acc[mi][1], ah[mi], bh[0][2], bh[0][3]);
            mma16816(acc[mi][2], ah[mi], bh[1][0], bh[1][1]);
            mma16816(acc[mi][3], ah[mi], bh[1][2], bh[1][3]);
            // hi*lo
            mma16816(acc[mi][0], ah[mi], bl[0][0], bl[0][1]);
            mma16816(acc[mi][1], ah[mi], bl[0][2], bl[0][3]);
            mma16816(acc[mi][2], ah[mi], bl[1][0], bl[1][1]);
            mma16816(acc[mi][3], ah[mi], bl[1][2], bl[1][3]);
            // lo*hi
            mma16816(acc[mi][0], al[mi], bh[0][0], bh[0][1]);
            mma16816(acc[mi][1], al[mi], bh[0][2], bh[0][3]);
            mma16816(acc[mi][2], al[mi], bh[1][0], bh[1][1]);
            mma16816(acc[mi][3], al[mi], bh[1][2], bh[1][3]);
        }
    }
}

__global__ void __launch_bounds__(256, 2)
kernA(const float* __restrict__ x, const float* __restrict__ mask,
      const float* __restrict__ nw, const float* __restrict__ nb,
      const float* __restrict__ Wl, const float* __restrict__ Wlg,
      const float* __restrict__ Wr, const float* __restrict__ Wrg,
      const float* __restrict__ Wog)
{
    extern __shared__ char raw[];
    SmemA4& sm = *reinterpret_cast<SmemA4*>(raw);
    const int tid = threadIdx.x;
    const int pos0 = blockIdx.x * 64;
    const int wid = tid >> 5, lid = tid & 31;

    if (tid < 128) { sm.nw[tid] = nw[tid]; sm.nb[tid] = nb[tid]; }
    if (tid < 64)  sm.mrow[tid] = mask[pos0 + tid];
    __syncthreads();

    // LayerNorm: warp wid -> rows wid*8..+7; lane covers cols 4*lid..4*lid+3
    #pragma unroll
    for (int rr = 0; rr < 8; rr++) {
        int r = wid * 8 + rr;
        float4 v = *(const float4*)(x + (size_t)(pos0 + r) * 128 + lid * 4);
        float s = v.x + v.y + v.z + v.w;
        float q = v.x * v.x + v.y * v.y + v.z * v.z + v.w * v.w;
        #pragma unroll
        for (int o = 16; o; o >>= 1) {
            s += __shfl_xor_sync(0xffffffffu, s, o);
            q += __shfl_xor_sync(0xffffffffu, q, o);
        }
        float mu = s * (1.f / 128.f);
        float rstd = rsqrtf(q * (1.f / 128.f) - mu * mu + 1e-5f);
        float4 nwv = *(const float4*)&sm.nw[lid * 4];
        float4 nbv = *(const float4*)&sm.nb[lid * 4];
        float y0 = (v.x - mu) * rstd * nwv.x + nbv.x;
        float y1 = (v.y - mu) * rstd * nwv.y + nbv.y;
        float y2 = (v.z - mu) * rstd * nwv.z + nbv.z;
        float y3 = (v.w - mu) * rstd * nwv.w + nbv.w;
        __nv_bfloat162 h01 = __floats2bfloat162_rn(y0, y1);
        __nv_bfloat162 h23 = __floats2bfloat162_rn(y2, y3);
        __nv_bfloat162 l01 = __floats2bfloat162_rn(y0 - __bfloat162float(h01.x),
                                                   y1 - __bfloat162float(h01.y));
        __nv_bfloat162 l23 = __floats2bfloat162_rn(y2 - __bfloat162float(h23.x),
                                                   y3 - __bfloat162float(h23.y));
        int kq = lid;                        // float4 column group
        uint32_t off = sw128(r, kq >> 1) + ((kq & 1) << 2);
        *(__nv_bfloat162*)(sm.xh + off)     = h01;
        *(__nv_bfloat162*)(sm.xh + off + 2) = h23;
        *(__nv_bfloat162*)(sm.xl + off)     = l01;
        *(__nv_bfloat162*)(sm.xl + off + 2) = l23;
    }
    __syncthreads();

    const int m0w = (wid >> 2) * 32;   // 0 or 32
    const int n0w = (wid & 3) * 32;    // 0,32,64,96
    const uint32_t bxh = (uint32_t)__cvta_generic_to_shared(sm.xh);
    const uint32_t bxl = (uint32_t)__cvta_generic_to_shared(sm.xl);
    const uint32_t bwh = (uint32_t)__cvta_generic_to_shared(sm.wh);
    const uint32_t bwl = (uint32_t)__cvta_generic_to_shared(sm.wl);
    float accV[2][4][4], accG[2][4][4];

    #pragma unroll 1
    for (int side = 0; side < 2; side++) {
        const float* Wv = side ? Wr  : Wl;
        const float* Wg = side ? Wrg : Wlg;
        __nv_bfloat16* dst = side ? g_right : g_left;

        stageW4(sm, Wv, tid); __syncthreads();
        gemm3(sm, accV, m0w, n0w, lid, bxh, bxl, bwh, bwl); __syncthreads();
        stageW4(sm, Wg, tid); __syncthreads();
        gemm3(sm, accG, m0w, n0w, lid, bxh, bxl, bwh, bwl);
        __syncthreads();                 // all wh/wl reads done (obf aliases wh)
        #pragma unroll
        for (int mt = 0; mt < 2; mt++) {
            int rA = m0w + mt * 16 + (lid >> 2);
            float mA = sm.mrow[rA], mB = sm.mrow[rA + 8];
            #pragma unroll
            for (int nt = 0; nt < 4; nt++) {
                int c = n0w + nt * 8 + 2 * (lid & 3);
                float v0 = accV[mt][nt][0] * mA * sigf(accG[mt][nt][0]);
                float v1 = accV[mt][nt][1] * mA * sigf(accG[mt][nt][1]);
                float v2 = accV[mt][nt][2] * mB * sigf(accG[mt][nt][2]);
                float v3 = accV[mt][nt][3] * mB * sigf(accG[mt][nt][3]);
                *(__nv_bfloat162*)&sm.obf[rA][c]     = __floats2bfloat162_rn(v0, v1);
                *(__nv_bfloat162*)&sm.obf[rA + 8][c] = __floats2bfloat162_rn(v2, v3);
            }
        }
        __syncthreads();
        #pragma unroll
        for (int t = 0; t < 32; t++) {   // transpose flush: [d][pos] planes
            int idx = tid + t * 256;
            int dch = idx >> 6, p = idx & 63;
            dst[(size_t)dch * NN + pos0 + p] = sm.obf[p][dch];
        }
        __syncthreads();
    }

    // ---- out_gate = sigmoid(LN(x)@Wog^T), stored [pos][h] fp32 ----
    stageW4(sm, Wog, tid); __syncthreads();
    gemm3(sm, accV, m0w, n0w, lid, bxh, bxl, bwh, bwl);
    #pragma unroll
    for (int mt = 0; mt < 2; mt++) {
        int rA = m0w + mt * 16 + (lid >> 2);
        #pragma unroll
        for (int nt = 0; nt < 4; nt++) {
            int c = n0w + nt * 8 + 2 * (lid & 3);
            float2 o0 = make_float2(sigf(accV[mt][nt][0]), sigf(accV[mt][nt][1]));
            float2 o1 = make_float2(sigf(accV[mt][nt][2]), sigf(accV[mt][nt][3]));
            *(float2*)(g_outgate + (size_t)(pos0 + rA) * 128 + c)     = o0;
            *(float2*)(g_outgate + (size_t)(pos0 + rA + 8) * 128 + c) = o1;
        }
    }
}

// =====================================================================
// Kernel B: per-channel batched GEMM  acc_d = L_d (384x384) @ R_d^T
// bf16 HMMA, 128x128 block tile, 64x32 warp tile (unchanged — passing)
// =====================================================================
__device__ __forceinline__ uint32_t swOff(int row, int chunk) {
    return (uint32_t)(row * 64 + ((chunk ^ (row & 7)) << 3));
}

__global__ void __launch_bounds__(256) kernB()
{
    __shared__ __nv_bfloat16 As[128 * 64];
    __shared__ __nv_bfloat16 Bs[128 * 64];
    const int tid = threadIdx.x;
    const int d  = blockIdx.z;
    const int i0 = blockIdx.y * 128;
    const int j0 = blockIdx.x * 128;
    const __nv_bfloat16* A = g_left  + (size_t)d * NN;
    const __nv_bfloat16* B = g_right + (size_t)d * NN;

    const int warp = tid >> 5, lane = tid & 31;
    const int m0 = (warp >> 2) * 64;
    const int n0 = (warp & 3) * 32;

    const uint32_t baseA = (uint32_t)__cvta_generic_to_shared(As);
    const uint32_t baseB = (uint32_t)__cvta_generic_to_shared(Bs);

    float acc[4][4][4];
    #pragma unroll
    for (int mi = 0; mi < 4; mi++)
        #pragma unroll
        for (int ni = 0; ni < 4; ni++)
            #pragma unroll
            for (int e = 0; e < 4; e++) acc[mi][ni][e] = 0.f;

    const int aRow = ((lane & 8) ? 8 : 0) + (lane & 7);
    const int aChk = (lane >> 4);
    const int bRow = ((lane & 16) ? 8 : 0) + (lane & 7);
    const int bChk = ((lane >> 3) & 1);

    for (int kb = 0; kb < NDIM; kb += 64) {
        __syncthreads();
        #pragma unroll
        for (int t = 0; t < 4; t++) {
            int idx = tid + t * 256;
            int r = idx >> 3, c = idx & 7;
            uint32_t so = swOff(r, c);
            *(uint4*)(As + so) = *(const uint4*)(A + (size_t)(i0 + r) * NDIM + kb + c * 8);
            *(uint4*)(Bs + so) = *(const uint4*)(B + (size_t)(j0 + r) * NDIM + kb + c * 8);
        }
        __syncthreads();

        #pragma unroll
        for (int kk = 0; kk < 64; kk += 16) {
            uint32_t af[4][4];
            #pragma unroll
            for (int mi = 0; mi < 4; mi++) {
                int row = m0 + mi * 16 + aRow;
                ldm4(af[mi], baseA + swOff(row, (kk >> 3) + aChk) * 2);
            }
            uint32_t bf[2][4];
            #pragma unroll
            for (int p = 0; p < 2; p++) {
                int row = n0 + p * 16 + bRow;
                ldm4(bf[p], baseB + swOff(row, (kk >> 3) + bChk) * 2);
            }
            #pragma unroll
            for (int mi = 0; mi < 4; mi++) {
                mma16816(acc[mi][0], af[mi], bf[0][0], bf[0][1]);
                mma16816(acc[mi][1], af[mi], bf[0][2], bf[0][3]);
                mma16816(acc[mi][2], af[mi], bf[1][0], bf[1][1]);
                mma16816(acc[mi][3], af[mi], bf[1][2], bf[1][3]);
            }
        }
    }

    __nv_bfloat16* C = g_accbf + (size_t)d * NN;
    const int r = lane >> 2, cp = (lane & 3) * 2;
    #pragma unroll
    for (int mi = 0; mi < 4; mi++)
        #pragma unroll
        for (int ni = 0; ni < 4; ni++) {
            int gi = i0 + m0 + mi * 16 + r;
            int gj = j0 + n0 + ni * 8 + cp;
            *(__nv_bfloat162*)(C + (size_t)gi * NDIM + gj) =
                __floats2bfloat162_rn(acc[mi][ni][0], acc[mi][ni][1]);
            *(__nv_bfloat162*)(C + (size_t)(gi + 8) * NDIM + gj) =
                __floats2bfloat162_rn(acc[mi][ni][2], acc[mi][ni][3]);
        }
}

// =====================================================================
// Kernel C: out-LN over H + out_gate + @W_out^T   (unchanged — passing)
// =====================================================================
struct SmemC {
    float s[64][132];
    float WoT[128][132];
    float onw[128];
    float onb[128];
};

__global__ void __launch_bounds__(512, 2)
kernC(const float* __restrict__ onw, const float* __restrict__ onb,
      const float* __restrict__ Wout, float* __restrict__ out)
{
    extern __shared__ char raw[];
    SmemC& sm = *reinterpret_cast<SmemC*>(raw);
    const int tid = threadIdx.x;
    const int pos0 = blockIdx.x * 64;

    if (tid < 128) { sm.onw[tid] = onw[tid]; sm.onb[tid] = onb[tid]; }
    #pragma unroll
    for (int t = 0; t < 32; t++) {
        int idx = tid + t * 512;
        int dd = idx >> 7, h = idx & 127;
        sm.WoT[h][dd] = Wout[idx];
    }
    #pragma unroll
    for (int t = 0; t < 16; t++) {
        int idx = tid + t * 512;
        int dch = idx >> 6, p = idx & 63;
        sm.s[p][dch] = __bfloat162float(g_accbf[(size_t)dch * NN + pos0 + p]);
    }
    __syncthreads();

    const int wid = tid >> 5, lid = tid & 31;
    #pragma unroll
    for (int pp = 0; pp < 4; pp++) {
        int p = wid * 4 + pp;
        float v[4]; float ssum = 0.f, q = 0.f;
        #pragma unroll
        for (int t = 0; t < 4; t++) {
            v[t] = sm.s[p][lid + 32 * t];
            ssum += v[t]; q += v[t] * v[t];
        }
        #pragma unroll
        for (int o = 16; o; o >>= 1) {
            ssum += __shfl_xor_sync(0xffffffffu, ssum, o);
            q    += __shfl_xor_sync(0xffffffffu, q, o);
        }
        float mu = ssum * (1.f / 128.f);
        float rstd = rsqrtf(q * (1.f / 128.f) - mu * mu + 1e-5f);
        const float* og = g_outgate + (size_t)(pos0 + p) * 128;
        #pragma unroll
        for (int t = 0; t < 4; t++) {
            int h = lid + 32 * t;
            float g = ((v[t] - mu) * rstd * sm.onw[h] + sm.onb[h]) * og[h];
            sm.s[p][h] = g;
        }
        __syncwarp();
        float4 a = make_float4(0.f, 0.f, 0.f, 0.f);
        #pragma unroll 8
        for (int h = 0; h < 128; h++) {
            float gs = sm.s[p][h];
            float4 w = *(const float4*)&sm.WoT[h][lid * 4];
            a.x += gs * w.x; a.y += gs * w.y; a.z += gs * w.z; a.w += gs * w.w;
        }
        *(float4*)(out + (size_t)(pos0 + p) * 128 + lid * 4) = a;
        __syncwarp();
    }
}

// =====================================================================
extern "C" void kernel_launch(void* const* d_in, const int* in_sizes, int n_in,
                              void* d_out, int out_size)
{
    (void)in_sizes; (void)n_in; (void)out_size;
    const float* x    = (const float*)d_in[0];
    const float* mask = (const float*)d_in[1];
    const float* nw   = (const float*)d_in[2];
    const float* nb   = (const float*)d_in[3];
    const float* Wl   = (const float*)d_in[4];
    const float* Wr   = (const float*)d_in[5];
    const float* Wlg  = (const float*)d_in[6];
    const float* Wrg  = (const float*)d_in[7];
    const float* Wog  = (const float*)d_in[8];
    const float* onw  = (const float*)d_in[9];
    const float* onb  = (const float*)d_in[10];
    const float* Wout = (const float*)d_in[11];
    float* out = (float*)d_out;

    cudaFuncSetAttribute(kernA, cudaFuncAttributeMaxDynamicSharedMemorySize, (int)sizeof(SmemA4));
    cudaFuncSetAttribute(kernC, cudaFuncAttributeMaxDynamicSharedMemorySize, (int)sizeof(SmemC));

    kernA<<<NN / 64, 256, sizeof(SmemA4)>>>(x, mask, nw, nb, Wl, Wlg, Wr, Wrg, Wog);
    kernB<<<dim3(3, 3, 128), 256>>>();
    kernC<<<NN / 64, 512, sizeof(SmemC)>>>(onw, onb, Wout, out);
}

// round 10
// speedup vs baseline: 3.7196x; 1.5966x over previous
#include <cuda_runtime.h>
#include <cuda_bf16.h>
#include <cstdint>

#define NDIM 384
#define NN   (NDIM * NDIM)   // 147456
#define DDIM 128

// ---- scratch (device globals; no allocation allowed) ----
__device__ __nv_bfloat16 g_left [(size_t)DDIM * NN];   // [d][i*N+k] bf16
__device__ __nv_bfloat16 g_right[(size_t)DDIM * NN];   // [d][j*N+k] bf16
__device__ float         g_outgate[(size_t)NN * DDIM]; // [pos][h] fp32
__device__ __nv_bfloat16 g_accbf[(size_t)DDIM * NN];   // [d][i*N+j] bf16 (einsum out)

__device__ __forceinline__ float sigf(float v) { return 1.f / (1.f + __expf(-v)); }

// ---- shared mma helpers ----
__device__ __forceinline__ void ldm4(uint32_t (&r)[4], uint32_t saddr) {
    asm volatile("ldmatrix.sync.aligned.m8n8.x4.shared.b16 {%0,%1,%2,%3}, [%4];"
        : "=r"(r[0]), "=r"(r[1]), "=r"(r[2]), "=r"(r[3]) : "r"(saddr));
}
__device__ __forceinline__ void mma16816(float (&d)[4], const uint32_t (&a)[4],
                                         uint32_t b0, uint32_t b1) {
    asm volatile("mma.sync.aligned.m16n8k16.row.col.f32.bf16.bf16.f32 "
        "{%0,%1,%2,%3}, {%4,%5,%6,%7}, {%8,%9}, {%0,%1,%2,%3};"
        : "+f"(d[0]), "+f"(d[1]), "+f"(d[2]), "+f"(d[3])
        : "r"(a[0]), "r"(a[1]), "r"(a[2]), "r"(a[3]), "r"(b0), "r"(b1));
}
__device__ __forceinline__ void cpa16(uint32_t dst, const void* src) {
    asm volatile("cp.async.cg.shared.global [%0], [%1], 16;" :: "r"(dst), "l"(src));
}
__device__ __forceinline__ void cpaCommit() { asm volatile("cp.async.commit_group;"); }

// 128-col swizzled offset (elements)
__device__ __forceinline__ uint32_t sw128(int row, int chunk) {
    return (uint32_t)(row * 128 + (((chunk & 7) ^ (row & 7)) << 3) + ((chunk & 8) << 3));
}

// 3-pass split gemm (bf16x3): acc[2][4][4] for a 32x32 warp tile, K=128
__device__ __forceinline__ void gemm3(float acc[2][4][4], int m0w, int n0w, int lane,
                                      uint32_t bxh, uint32_t bxl,
                                      uint32_t bwh, uint32_t bwl) {
    #pragma unroll
    for (int mi = 0; mi < 2; mi++)
        #pragma unroll
        for (int ni = 0; ni < 4; ni++)
            #pragma unroll
            for (int e = 0; e < 4; e++) acc[mi][ni][e] = 0.f;

    const int aRow = ((lane & 8) ? 8 : 0) + (lane & 7);
    const int aChk = (lane >> 4);
    const int bRow = ((lane & 16) ? 8 : 0) + (lane & 7);
    const int bChk = (lane >> 3) & 1;

    #pragma unroll
    for (int ks = 0; ks < 8; ks++) {
        uint32_t ah[2][4], al[2][4], bh[2][4], bl[2][4];
        #pragma unroll
        for (int mi = 0; mi < 2; mi++) {
            uint32_t off = sw128(m0w + mi * 16 + aRow, ks * 2 + aChk) * 2;
            ldm4(ah[mi], bxh + off);
            ldm4(al[mi], bxl + off);
        }
        #pragma unroll
        for (int p = 0; p < 2; p++) {
            uint32_t off = sw128(n0w + p * 16 + bRow, ks * 2 + bChk) * 2;
            ldm4(bh[p], bwh + off);
            ldm4(bl[p], bwl + off);
        }
        #pragma unroll
        for (int mi = 0; mi < 2; mi++) {
            mma16816(acc[mi][0], ah[mi], bh[0][0], bh[0][1]);
            mma16816(acc[mi][1], ah[mi], bh[0][2], bh[0][3]);
            mma16816(acc[mi][2], ah[mi], bh[1][0], bh[1][1]);
            mma16816(acc[mi][3], ah[mi], bh[1][2], bh[1][3]);
            mma16816(acc[mi][0], ah[mi], bl[0][0], bl[0][1]);
            mma16816(acc[mi][1], ah[mi], bl[0][2], bl[0][3]);
            mma16816(acc[mi][2], ah[mi], bl[1][0], bl[1][1]);
            mma16816(acc[mi][3], ah[mi], bl[1][2], bl[1][3]);
            mma16816(acc[mi][0], al[mi], bh[0][0], bh[0][1]);
            mma16816(acc[mi][1], al[mi], bh[0][2], bh[0][3]);
            mma16816(acc[mi][2], al[mi], bh[1][0], bh[1][1]);
            mma16816(acc[mi][3], al[mi], bh[1][2], bh[1][3]);
        }
    }
}

// =====================================================================
// Kernel A: LayerNorm + 5 projections + gating — bf16x3 split HMMA
// (unchanged from R8 — passing at 291 us)
// =====================================================================
struct SmemA4 {
    __nv_bfloat16 xh[64 * 128];
    __nv_bfloat16 xl[64 * 128];
    union {
        __nv_bfloat16 wh[128 * 128];
        __nv_bfloat16 obf[64][130];
    };
    __nv_bfloat16 wl[128 * 128];
    float mrow[64];
    float nw[128];
    float nb[128];
};

__device__ __forceinline__ void stageW4(__nv_bfloat16* wh, __nv_bfloat16* wl,
                                        const float* __restrict__ W, int tid) {
    #pragma unroll
    for (int t = 0; t < 16; t++) {
        int idx = tid + t * 256;
        int h = idx >> 5, kq = idx & 31;
        float4 w = *(const float4*)(W + h * 128 + kq * 4);
        __nv_bfloat162 h01 = __floats2bfloat162_rn(w.x, w.y);
        __nv_bfloat162 h23 = __floats2bfloat162_rn(w.z, w.w);
        __nv_bfloat162 l01 = __floats2bfloat162_rn(w.x - __bfloat162float(h01.x),
                                                   w.y - __bfloat162float(h01.y));
        __nv_bfloat162 l23 = __floats2bfloat162_rn(w.z - __bfloat162float(h23.x),
                                                   w.w - __bfloat162float(h23.y));
        uint32_t off = sw128(h, kq >> 1) + ((kq & 1) << 2);
        *(__nv_bfloat162*)(wh + off)     = h01;
        *(__nv_bfloat162*)(wh + off + 2) = h23;
        *(__nv_bfloat162*)(wl + off)     = l01;
        *(__nv_bfloat162*)(wl + off + 2) = l23;
    }
}

__global__ void __launch_bounds__(256, 2)
kernA(const float* __restrict__ x, const float* __restrict__ mask,
      const float* __restrict__ nw, const float* __restrict__ nb,
      const float* __restrict__ Wl, const float* __restrict__ Wlg,
      const float* __restrict__ Wr, const float* __restrict__ Wrg,
      const float* __restrict__ Wog)
{
    extern __shared__ char raw[];
    SmemA4& sm = *reinterpret_cast<SmemA4*>(raw);
    const int tid = threadIdx.x;
    const int pos0 = blockIdx.x * 64;
    const int wid = tid >> 5, lid = tid & 31;

    if (tid < 128) { sm.nw[tid] = nw[tid]; sm.nb[tid] = nb[tid]; }
    if (tid < 64)  sm.mrow[tid] = mask[pos0 + tid];
    __syncthreads();

    #pragma unroll
    for (int rr = 0; rr < 8; rr++) {
        int r = wid * 8 + rr;
        float4 v = *(const float4*)(x + (size_t)(pos0 + r) * 128 + lid * 4);
        float s = v.x + v.y + v.z + v.w;
        float q = v.x * v.x + v.y * v.y + v.z * v.z + v.w * v.w;
        #pragma unroll
        for (int o = 16; o; o >>= 1) {
            s += __shfl_xor_sync(0xffffffffu, s, o);
            q += __shfl_xor_sync(0xffffffffu, q, o);
        }
        float mu = s * (1.f / 128.f);
        float rstd = rsqrtf(q * (1.f / 128.f) - mu * mu + 1e-5f);
        float4 nwv = *(const float4*)&sm.nw[lid * 4];
        float4 nbv = *(const float4*)&sm.nb[lid * 4];
        float y0 = (v.x - mu) * rstd * nwv.x + nbv.x;
        float y1 = (v.y - mu) * rstd * nwv.y + nbv.y;
        float y2 = (v.z - mu) * rstd * nwv.z + nbv.z;
        float y3 = (v.w - mu) * rstd * nwv.w + nbv.w;
        __nv_bfloat162 h01 = __floats2bfloat162_rn(y0, y1);
        __nv_bfloat162 h23 = __floats2bfloat162_rn(y2, y3);
        __nv_bfloat162 l01 = __floats2bfloat162_rn(y0 - __bfloat162float(h01.x),
                                                   y1 - __bfloat162float(h01.y));
        __nv_bfloat162 l23 = __floats2bfloat162_rn(y2 - __bfloat162float(h23.x),
                                                   y3 - __bfloat162float(h23.y));
        uint32_t off = sw128(r, lid >> 1) + ((lid & 1) << 2);
        *(__nv_bfloat162*)(sm.xh + off)     = h01;
        *(__nv_bfloat162*)(sm.xh + off + 2) = h23;
        *(__nv_bfloat162*)(sm.xl + off)     = l01;
        *(__nv_bfloat162*)(sm.xl + off + 2) = l23;
    }
    __syncthreads();

    const int m0w = (wid >> 2) * 32;
    const int n0w = (wid & 3) * 32;
    const uint32_t bxh = (uint32_t)__cvta_generic_to_shared(sm.xh);
    const uint32_t bxl = (uint32_t)__cvta_generic_to_shared(sm.xl);
    const uint32_t bwh = (uint32_t)__cvta_generic_to_shared(sm.wh);
    const uint32_t bwl = (uint32_t)__cvta_generic_to_shared(sm.wl);
    float accV[2][4][4], accG[2][4][4];

    #pragma unroll 1
    for (int side = 0; side < 2; side++) {
        const float* Wv = side ? Wr  : Wl;
        const float* Wg = side ? Wrg : Wlg;
        __nv_bfloat16* dst = side ? g_right : g_left;

        stageW4(sm.wh, sm.wl, Wv, tid); __syncthreads();
        gemm3(accV, m0w, n0w, lid, bxh, bxl, bwh, bwl); __syncthreads();
        stageW4(sm.wh, sm.wl, Wg, tid); __syncthreads();
        gemm3(accG, m0w, n0w, lid, bxh, bxl, bwh, bwl);
        __syncthreads();
        #pragma unroll
        for (int mt = 0; mt < 2; mt++) {
            int rA = m0w + mt * 16 + (lid >> 2);
            float mA = sm.mrow[rA], mB = sm.mrow[rA + 8];
            #pragma unroll
            for (int nt = 0; nt < 4; nt++) {
                int c = n0w + nt * 8 + 2 * (lid & 3);
                float v0 = accV[mt][nt][0] * mA * sigf(accG[mt][nt][0]);
                float v1 = accV[mt][nt][1] * mA * sigf(accG[mt][nt][1]);
                float v2 = accV[mt][nt][2] * mB * sigf(accG[mt][nt][2]);
                float v3 = accV[mt][nt][3] * mB * sigf(accG[mt][nt][3]);
                *(__nv_bfloat162*)&sm.obf[rA][c]     = __floats2bfloat162_rn(v0, v1);
                *(__nv_bfloat162*)&sm.obf[rA + 8][c] = __floats2bfloat162_rn(v2, v3);
            }
        }
        __syncthreads();
        #pragma unroll
        for (int t = 0; t < 32; t++) {
            int idx = tid + t * 256;
            int dch = idx >> 6, p = idx & 63;
            dst[(size_t)dch * NN + pos0 + p] = sm.obf[p][dch];
        }
        __syncthreads();
    }

    stageW4(sm.wh, sm.wl, Wog, tid); __syncthreads();
    gemm3(accV, m0w, n0w, lid, bxh, bxl, bwh, bwl);
    #pragma unroll
    for (int mt = 0; mt < 2; mt++) {
        int rA = m0w + mt * 16 + (lid >> 2);
        #pragma unroll
        for (int nt = 0; nt < 4; nt++) {
            int c = n0w + nt * 8 + 2 * (lid & 3);
            float2 o0 = make_float2(sigf(accV[mt][nt][0]), sigf(accV[mt][nt][1]));
            float2 o1 = make_float2(sigf(accV[mt][nt][2]), sigf(accV[mt][nt][3]));
            *(float2*)(g_outgate + (size_t)(pos0 + rA) * 128 + c)     = o0;
            *(float2*)(g_outgate + (size_t)(pos0 + rA + 8) * 128 + c) = o1;
        }
    }
}

// =====================================================================
// Kernel B: per-channel batched GEMM  acc_d = L_d (384x384) @ R_d^T
// bf16 HMMA + cp.async 2-stage double buffer, dynamic smem 64 KB
// =====================================================================
__device__ __forceinline__ uint32_t swOff(int row, int chunk) {
    return (uint32_t)(row * 64 + ((chunk ^ (row & 7)) << 3));
}

__global__ void __launch_bounds__(256) kernB()
{
    extern __shared__ __nv_bfloat16 smb[];   // [stage][As 8192 | Bs 8192]
    const int tid = threadIdx.x;
    const int d  = blockIdx.z;
    const int i0 = blockIdx.y * 128;
    const int j0 = blockIdx.x * 128;
    const __nv_bfloat16* A = g_left  + (size_t)d * NN;
    const __nv_bfloat16* B = g_right + (size_t)d * NN;

    const int warp = tid >> 5, lane = tid & 31;
    const int m0 = (warp >> 2) * 64;
    const int n0 = (warp & 3) * 32;
    const uint32_t base = (uint32_t)__cvta_generic_to_shared(smb);

    float acc[4][4][4];
    #pragma unroll
    for (int mi = 0; mi < 4; mi++)
        #pragma unroll
        for (int ni = 0; ni < 4; ni++)
            #pragma unroll
            for (int e = 0; e < 4; e++) acc[mi][ni][e] = 0.f;

    const int aRow = ((lane & 8) ? 8 : 0) + (lane & 7);
    const int aChk = (lane >> 4);
    const int bRow = ((lane & 16) ? 8 : 0) + (lane & 7);
    const int bChk = ((lane >> 3) & 1);

    // async load of k-tile kb into stage st
    auto loadTile = [&](int st, int kb) {
        uint32_t sbase = base + (uint32_t)st * 32768;   // 16384 elems * 2 B
        #pragma unroll
        for (int t = 0; t < 4; t++) {
            int idx = tid + t * 256;
            int r = idx >> 3, c = idx & 7;
            uint32_t so = swOff(r, c) * 2;
            cpa16(sbase + so,         A + (size_t)(i0 + r) * NDIM + kb + c * 8);
            cpa16(sbase + 16384 + so, B + (size_t)(j0 + r) * NDIM + kb + c * 8);
        }
        cpaCommit();
    };

    loadTile(0, 0);
    #pragma unroll 1
    for (int k = 0; k < 6; k++) {
        const int cur = k & 1;
        if (k < 5) loadTile(1 - cur, (k + 1) * 64);
        if (k < 5) asm volatile("cp.async.wait_group 1;");
        else       asm volatile("cp.async.wait_group 0;");
        __syncthreads();

        const uint32_t sA = base + (uint32_t)cur * 32768;
        const uint32_t sB = sA + 16384;
        #pragma unroll
        for (int kk = 0; kk < 64; kk += 16) {
            uint32_t af[4][4];
            #pragma unroll
            for (int mi = 0; mi < 4; mi++) {
                int row = m0 + mi * 16 + aRow;
                ldm4(af[mi], sA + swOff(row, (kk >> 3) + aChk) * 2);
            }
            uint32_t bf[2][4];
            #pragma unroll
            for (int p = 0; p < 2; p++) {
                int row = n0 + p * 16 + bRow;
                ldm4(bf[p], sB + swOff(row, (kk >> 3) + bChk) * 2);
            }
            #pragma unroll
            for (int mi = 0; mi < 4; mi++) {
                mma16816(acc[mi][0], af[mi], bf[0][0], bf[0][1]);
                mma16816(acc[mi][1], af[mi], bf[0][2], bf[0][3]);
                mma16816(acc[mi][2], af[mi], bf[1][0], bf[1][1]);
                mma16816(acc[mi][3], af[mi], bf[1][2], bf[1][3]);
            }
        }
        __syncthreads();
    }

    __nv_bfloat16* C = g_accbf + (size_t)d * NN;
    const int r = lane >> 2, cp = (lane & 3) * 2;
    #pragma unroll
    for (int mi = 0; mi < 4; mi++)
        #pragma unroll
        for (int ni = 0; ni < 4; ni++) {
            int gi = i0 + m0 + mi * 16 + r;
            int gj = j0 + n0 + ni * 8 + cp;
            *(__nv_bfloat162*)(C + (size_t)gi * NDIM + gj) =
                __floats2bfloat162_rn(acc[mi][ni][0], acc[mi][ni][1]);
            *(__nv_bfloat162*)(C + (size_t)(gi + 8) * NDIM + gj) =
                __floats2bfloat162_rn(acc[mi][ni][2], acc[mi][ni][3]);
        }
}

// =====================================================================
// Kernel C: out-LN over H + out_gate, then @W_out^T via bf16x3 HMMA
// 256 threads, 64 positions per block, 2 CTAs/SM
// =====================================================================
struct SmemC2 {
    __nv_bfloat16 xh[64 * 128];          // gated activations hi  16 KB
    __nv_bfloat16 xl[64 * 128];          // gated activations lo  16 KB
    union {
        float s[64][132];                // einsum tile fp32      33.8 KB
        __nv_bfloat16 wh[128 * 128];     // W_out hi (aliases s)  32 KB
    };
    __nv_bfloat16 wl[128 * 128];         // W_out lo              32 KB
    float onw[128];
    float onb[128];
};

__global__ void __launch_bounds__(256, 2)
kernC(const float* __restrict__ onw, const float* __restrict__ onb,
      const float* __restrict__ Wout, float* __restrict__ out)
{
    extern __shared__ char raw[];
    SmemC2& sm = *reinterpret_cast<SmemC2*>(raw);
    const int tid = threadIdx.x;
    const int pos0 = blockIdx.x * 64;
    const int wid = tid >> 5, lid = tid & 31;

    if (tid < 128) { sm.onw[tid] = onw[tid]; sm.onb[tid] = onb[tid]; }
    #pragma unroll
    for (int t = 0; t < 32; t++) {       // gather 128 d-planes -> [pos][h] tile
        int idx = tid + t * 256;
        int dch = idx >> 6, p = idx & 63;
        sm.s[p][dch] = __bfloat162float(g_accbf[(size_t)dch * NN + pos0 + p]);
    }
    __syncthreads();

    // out-LN + gate, split to hi/lo bf16 fragments (warp wid -> rows wid*8..+7)
    #pragma unroll
    for (int rr = 0; rr < 8; rr++) {
        int p = wid * 8 + rr;
        float4 v = *(const float4*)&sm.s[p][lid * 4];
        float ssum = v.x + v.y + v.z + v.w;
        float q = v.x * v.x + v.y * v.y + v.z * v.z + v.w * v.w;
        #pragma unroll
        for (int o = 16; o; o >>= 1) {
            ssum += __shfl_xor_sync(0xffffffffu, ssum, o);
            q    += __shfl_xor_sync(0xffffffffu, q, o);
        }
        float mu = ssum * (1.f / 128.f);
        float rstd = rsqrtf(q * (1.f / 128.f) - mu * mu + 1e-5f);
        float4 wv = *(const float4*)&sm.onw[lid * 4];
        float4 bv = *(const float4*)&sm.onb[lid * 4];
        float4 og = *(const float4*)(g_outgate + (size_t)(pos0 + p) * 128 + lid * 4);
        float y0 = ((v.x - mu) * rstd * wv.x + bv.x) * og.x;
        float y1 = ((v.y - mu) * rstd * wv.y + bv.y) * og.y;
        float y2 = ((v.z - mu) * rstd * wv.z + bv.z) * og.z;
        float y3 = ((v.w - mu) * rstd * wv.w + bv.w) * og.w;
        __nv_bfloat162 h01 = __floats2bfloat162_rn(y0, y1);
        __nv_bfloat162 h23 = __floats2bfloat162_rn(y2, y3);
        __nv_bfloat162 l01 = __floats2bfloat162_rn(y0 - __bfloat162float(h01.x),
                                                   y1 - __bfloat162float(h01.y));
        __nv_bfloat162 l23 = __floats2bfloat162_rn(y2 - __bfloat162float(h23.x),
                                                   y3 - __bfloat162float(h23.y));
        uint32_t off = sw128(p, lid >> 1) + ((lid & 1) << 2);
        *(__nv_bfloat162*)(sm.xh + off)     = h01;
        *(__nv_bfloat162*)(sm.xh + off + 2) = h23;
        *(__nv_bfloat162*)(sm.xl + off)     = l01;
        *(__nv_bfloat162*)(sm.xl + off + 2) = l23;
    }
    __syncthreads();                     // all s reads done (wh aliases s)

    // stage W_out [D=128][H=128] row-major -> (wh, wl); n=dd, k=h
    stageW4(sm.wh, sm.wl, Wout, tid);
    __syncthreads();

    const int m0w = (wid >> 2) * 32;     // 0 or 32 (positions)
    const int n0w = (wid & 3) * 32;      // 0..96   (output dd)
    const uint32_t bxh = (uint32_t)__cvta_generic_to_shared(sm.xh);
    const uint32_t bxl = (uint32_t)__cvta_generic_to_shared(sm.xl);
    const uint32_t bwh = (uint32_t)__cvta_generic_to_shared(sm.wh);
    const uint32_t bwl = (uint32_t)__cvta_generic_to_shared(sm.wl);
    float acc[2][4][4];
    gemm3(acc, m0w, n0w, lid, bxh, bxl, bwh, bwl);

    #pragma unroll
    for (int mt = 0; mt < 2; mt++) {
        int rA = m0w + mt * 16 + (lid >> 2);
        #pragma unroll
        for (int nt = 0; nt < 4; nt++) {
            int c = n0w + nt * 8 + 2 * (lid & 3);
            *(float2*)(out + (size_t)(pos0 + rA) * 128 + c) =
                make_float2(acc[mt][nt][0], acc[mt][nt][1]);
            *(float2*)(out + (size_t)(pos0 + rA + 8) * 128 + c) =
                make_float2(acc[mt][nt][2], acc[mt][nt][3]);
        }
    }
}

// =====================================================================
extern "C" void kernel_launch(void* const* d_in, const int* in_sizes, int n_in,
                              void* d_out, int out_size)
{
    (void)in_sizes; (void)n_in; (void)out_size;
    const float* x    = (const float*)d_in[0];
    const float* mask = (const float*)d_in[1];
    const float* nw   = (const float*)d_in[2];
    const float* nb   = (const float*)d_in[3];
    const float* Wl   = (const float*)d_in[4];
    const float* Wr   = (const float*)d_in[5];
    const float* Wlg  = (const float*)d_in[6];
    const float* Wrg  = (const float*)d_in[7];
    const float* Wog  = (const float*)d_in[8];
    const float* onw  = (const float*)d_in[9];
    const float* onb  = (const float*)d_in[10];
    const float* Wout = (const float*)d_in[11];
    float* out = (float*)d_out;

    cudaFuncSetAttribute(kernA, cudaFuncAttributeMaxDynamicSharedMemorySize, (int)sizeof(SmemA4));
    cudaFuncSetAttribute(kernB, cudaFuncAttributeMaxDynamicSharedMemorySize, 65536);
    cudaFuncSetAttribute(kernC, cudaFuncAttributeMaxDynamicSharedMemorySize, (int)sizeof(SmemC2));

    kernA<<<NN / 64, 256, sizeof(SmemA4)>>>(x, mask, nw, nb, Wl, Wlg, Wr, Wrg, Wog);
    kernB<<<dim3(3, 3, 128), 256, 65536>>>();
    kernC<<<NN / 64, 256, sizeof(SmemC2)>>>(onw, onb, Wout, out);
}

// round 11
// speedup vs baseline: 3.7876x; 1.0183x over previous
#include <cuda_runtime.h>
#include <cuda_bf16.h>
#include <cstdint>

#define NDIM 384
#define NN   (NDIM * NDIM)   // 147456
#define DDIM 128

// ---- scratch (device globals; no allocation allowed) ----
__device__ __nv_bfloat16 g_left [(size_t)DDIM * NN];   // [d][i*N+k] bf16
__device__ __nv_bfloat16 g_right[(size_t)DDIM * NN];   // [d][j*N+k] bf16
__device__ float         g_outgate[(size_t)NN * DDIM]; // [pos][h] fp32
__device__ __nv_bfloat16 g_accbf[(size_t)DDIM * NN];   // [d][i*N+j] bf16 (einsum out)
__device__ __nv_bfloat16 g_wsp[5 * 32768];             // pre-split weights, frag layout
                                                       // [w][0:16384)=hi [16384:32768)=lo

__device__ __forceinline__ float sigf(float v) { return 1.f / (1.f + __expf(-v)); }

// ---- shared mma helpers ----
__device__ __forceinline__ void ldm4(uint32_t (&r)[4], uint32_t saddr) {
    asm volatile("ldmatrix.sync.aligned.m8n8.x4.shared.b16 {%0,%1,%2,%3}, [%4];"
        : "=r"(r[0]), "=r"(r[1]), "=r"(r[2]), "=r"(r[3]) : "r"(saddr));
}
__device__ __forceinline__ void mma16816(float (&d)[4], const uint32_t (&a)[4],
                                         uint32_t b0, uint32_t b1) {
    asm volatile("mma.sync.aligned.m16n8k16.row.col.f32.bf16.bf16.f32 "
        "{%0,%1,%2,%3}, {%4,%5,%6,%7}, {%8,%9}, {%0,%1,%2,%3};"
        : "+f"(d[0]), "+f"(d[1]), "+f"(d[2]), "+f"(d[3])
        : "r"(a[0]), "r"(a[1]), "r"(a[2]), "r"(a[3]), "r"(b0), "r"(b1));
}
__device__ __forceinline__ void cpa16(uint32_t dst, const void* src) {
    asm volatile("cp.async.cg.shared.global [%0], [%1], 16;" :: "r"(dst), "l"(src));
}
__device__ __forceinline__ void cpaCommit() { asm volatile("cp.async.commit_group;"); }

// 128-col swizzled offset (elements)
__device__ __forceinline__ uint32_t sw128(int row, int chunk) {
    return (uint32_t)(row * 128 + (((chunk & 7) ^ (row & 7)) << 3) + ((chunk & 8) << 3));
}

// 3-pass split gemm (bf16x3): acc[2][4][4] for a 32x32 warp tile, K=128
__device__ __forceinline__ void gemm3(float acc[2][4][4], int m0w, int n0w, int lane,
                                      uint32_t bxh, uint32_t bxl,
                                      uint32_t bwh, uint32_t bwl) {
    #pragma unroll
    for (int mi = 0; mi < 2; mi++)
        #pragma unroll
        for (int ni = 0; ni < 4; ni++)
            #pragma unroll
            for (int e = 0; e < 4; e++) acc[mi][ni][e] = 0.f;

    const int aRow = ((lane & 8) ? 8 : 0) + (lane & 7);
    const int aChk = (lane >> 4);
    const int bRow = ((lane & 16) ? 8 : 0) + (lane & 7);
    const int bChk = (lane >> 3) & 1;

    #pragma unroll
    for (int ks = 0; ks < 8; ks++) {
        uint32_t ah[2][4], al[2][4], bh[2][4], bl[2][4];
        #pragma unroll
        for (int mi = 0; mi < 2; mi++) {
            uint32_t off = sw128(m0w + mi * 16 + aRow, ks * 2 + aChk) * 2;
            ldm4(ah[mi], bxh + off);
            ldm4(al[mi], bxl + off);
        }
        #pragma unroll
        for (int p = 0; p < 2; p++) {
            uint32_t off = sw128(n0w + p * 16 + bRow, ks * 2 + bChk) * 2;
            ldm4(bh[p], bwh + off);
            ldm4(bl[p], bwl + off);
        }
        #pragma unroll
        for (int mi = 0; mi < 2; mi++) {
            mma16816(acc[mi][0], ah[mi], bh[0][0], bh[0][1]);
            mma16816(acc[mi][1], ah[mi], bh[0][2], bh[0][3]);
            mma16816(acc[mi][2], ah[mi], bh[1][0], bh[1][1]);
            mma16816(acc[mi][3], ah[mi], bh[1][2], bh[1][3]);
            mma16816(acc[mi][0], ah[mi], bl[0][0], bl[0][1]);
            mma16816(acc[mi][1], ah[mi], bl[0][2], bl[0][3]);
            mma16816(acc[mi][2], ah[mi], bl[1][0], bl[1][1]);
            mma16816(acc[mi][3], ah[mi], bl[1][2], bl[1][3]);
            mma16816(acc[mi][0], al[mi], bh[0][0], bh[0][1]);
            mma16816(acc[mi][1], al[mi], bh[0][2], bh[0][3]);
            mma16816(acc[mi][2], al[mi], bh[1][0], bh[1][1]);
            mma16816(acc[mi][3], al[mi], bh[1][2], bh[1][3]);
        }
    }
}

// =====================================================================
// Kernel W: pre-split all 5 projection weights into bf16 hi/lo pairs,
// stored directly in the swizzled fragment layout. grid(5) x 256.
// =====================================================================
__global__ void __launch_bounds__(256) kernW(
    const float* __restrict__ Wl, const float* __restrict__ Wlg,
    const float* __restrict__ Wr, const float* __restrict__ Wrg,
    const float* __restrict__ Wog)
{
    const float* W = (blockIdx.x == 0) ? Wl : (blockIdx.x == 1) ? Wlg :
                     (blockIdx.x == 2) ? Wr : (blockIdx.x == 3) ? Wrg : Wog;
    __nv_bfloat16* dh = g_wsp + (size_t)blockIdx.x * 32768;
    __nv_bfloat16* dl = dh + 16384;
    const int tid = threadIdx.x;
    #pragma unroll
    for (int t = 0; t < 16; t++) {
        int idx = tid + t * 256;            // float4 index, 4096 total
        int h = idx >> 5, kq = idx & 31;
        float4 w = *(const float4*)(W + h * 128 + kq * 4);
        __nv_bfloat162 h01 = __floats2bfloat162_rn(w.x, w.y);
        __nv_bfloat162 h23 = __floats2bfloat162_rn(w.z, w.w);
        __nv_bfloat162 l01 = __floats2bfloat162_rn(w.x - __bfloat162float(h01.x),
                                                   w.y - __bfloat162float(h01.y));
        __nv_bfloat162 l23 = __floats2bfloat162_rn(w.z - __bfloat162float(h23.x),
                                                   w.w - __bfloat162float(h23.y));
        uint32_t off = sw128(h, kq >> 1) + ((kq & 1) << 2);
        *(__nv_bfloat162*)(dh + off)     = h01;
        *(__nv_bfloat162*)(dh + off + 2) = h23;
        *(__nv_bfloat162*)(dl + off)     = l01;
        *(__nv_bfloat162*)(dl + off + 2) = l23;
    }
}

// =====================================================================
// Kernel A v4: LN + 5 projections + gating — bf16x3 HMMA,
// 512 threads, 128 rows/block, double-buffered cp.async weight stream
// =====================================================================
struct SmemA5 {
    __nv_bfloat16 xh[128 * 128];        // 32 KB
    __nv_bfloat16 xl[128 * 128];        // 32 KB
    __nv_bfloat16 wbuf[2][32768];       // 2 x 64 KB (hi|lo)
    __nv_bfloat16 obf[128][130];        // 33.3 KB
    float mrow[128];
    float nw[128];
    float nb[128];
};   // ~231.4 KB

__global__ void __launch_bounds__(512, 1)
kernA(const float* __restrict__ x, const float* __restrict__ mask,
      const float* __restrict__ nw, const float* __restrict__ nb)
{
    extern __shared__ char raw[];
    SmemA5& sm = *reinterpret_cast<SmemA5*>(raw);
    const int tid = threadIdx.x;
    const int pos0 = blockIdx.x * 128;
    const int wid = tid >> 5, lid = tid & 31;

    const uint32_t bW = (uint32_t)__cvta_generic_to_shared(sm.wbuf);
    // linear copy of pre-split weight w into stage st (layout preserved)
    auto cpW = [&](int st, int w) {
        const __nv_bfloat16* src = g_wsp + (size_t)w * 32768;
        uint32_t dst = bW + (uint32_t)st * 65536;
        #pragma unroll
        for (int t = 0; t < 8; t++) {
            int c = tid + t * 512;          // 16B chunk index, 4096 total
            cpa16(dst + c * 16, src + c * 8);
        }
        cpaCommit();
    };

    cpW(0, 0);                              // W0 = Wl  [g0]

    if (tid < 128) { sm.nw[tid] = nw[tid]; sm.nb[tid] = nb[tid]; sm.mrow[tid] = mask[pos0 + tid]; }
    __syncthreads();                        // nw/nb visible for LN

    // LayerNorm: warp wid -> rows wid*8..+7 (16 warps x 8 = 128 rows)
    #pragma unroll
    for (int rr = 0; rr < 8; rr++) {
        int r = wid * 8 + rr;
        float4 v = *(const float4*)(x + (size_t)(pos0 + r) * 128 + lid * 4);
        float s = v.x + v.y + v.z + v.w;
        float q = v.x * v.x + v.y * v.y + v.z * v.z + v.w * v.w;
        #pragma unroll
        for (int o = 16; o; o >>= 1) {
            s += __shfl_xor_sync(0xffffffffu, s, o);
            q += __shfl_xor_sync(0xffffffffu, q, o);
        }
        float mu = s * (1.f / 128.f);
        float rstd = rsqrtf(q * (1.f / 128.f) - mu * mu + 1e-5f);
        float4 nwv = *(const float4*)&sm.nw[lid * 4];
        float4 nbv = *(const float4*)&sm.nb[lid * 4];
        float y0 = (v.x - mu) * rstd * nwv.x + nbv.x;
        float y1 = (v.y - mu) * rstd * nwv.y + nbv.y;
        float y2 = (v.z - mu) * rstd * nwv.z + nbv.z;
        float y3 = (v.w - mu) * rstd * nwv.w + nbv.w;
        __nv_bfloat162 h01 = __floats2bfloat162_rn(y0, y1);
        __nv_bfloat162 h23 = __floats2bfloat162_rn(y2, y3);
        __nv_bfloat162 l01 = __floats2bfloat162_rn(y0 - __bfloat162float(h01.x),
                                                   y1 - __bfloat162float(h01.y));
        __nv_bfloat162 l23 = __floats2bfloat162_rn(y2 - __bfloat162float(h23.x),
                                                   y3 - __bfloat162float(h23.y));
        uint32_t off = sw128(r, lid >> 1) + ((lid & 1) << 2);
        *(__nv_bfloat162*)(sm.xh + off)     = h01;
        *(__nv_bfloat162*)(sm.xh + off + 2) = h23;
        *(__nv_bfloat162*)(sm.xl + off)     = l01;
        *(__nv_bfloat162*)(sm.xl + off + 2) = l23;
    }
    asm volatile("cp.async.wait_group 0;");  // g0 done: W0 resident
    __syncthreads();

    const int m0w = (wid >> 2) * 32;    // 0..96 (4x4 warp grid)
    const int n0w = (wid & 3) * 32;
    const uint32_t bxh = (uint32_t)__cvta_generic_to_shared(sm.xh);
    const uint32_t bxl = (uint32_t)__cvta_generic_to_shared(sm.xl);
    float accV[2][4][4], accG[2][4][4];

    auto wbh = [&](int st) { return bW + (uint32_t)st * 65536; };
    auto wbl = [&](int st) { return bW + (uint32_t)st * 65536 + 32768; };

    auto combineFlush = [&](__nv_bfloat16* dst) {
        #pragma unroll
        for (int mt = 0; mt < 2; mt++) {
            int rA = m0w + mt * 16 + (lid >> 2);
            float mA = sm.mrow[rA], mB = sm.mrow[rA + 8];
            #pragma unroll
            for (int nt = 0; nt < 4; nt++) {
                int c = n0w + nt * 8 + 2 * (lid & 3);
                float v0 = accV[mt][nt][0] * mA * sigf(accG[mt][nt][0]);
                float v1 = accV[mt][nt][1] * mA * sigf(accG[mt][nt][1]);
                float v2 = accV[mt][nt][2] * mB * sigf(accG[mt][nt][2]);
                float v3 = accV[mt][nt][3] * mB * sigf(accG[mt][nt][3]);
                *(__nv_bfloat162*)&sm.obf[rA][c]     = __floats2bfloat162_rn(v0, v1);
                *(__nv_bfloat162*)&sm.obf[rA + 8][c] = __floats2bfloat162_rn(v2, v3);
            }
        }
        __syncthreads();
        #pragma unroll
        for (int t = 0; t < 32; t++) {       // transpose flush: [d][pos] planes
            int idx = tid + t * 512;
            int dch = idx >> 7, p = idx & 127;
            dst[(size_t)dch * NN + pos0 + p] = sm.obf[p][dch];
        }
        __syncthreads();
    };

    // ---- left pair: gemm Wl (B0) || prefetch Wlg->B1; gemm Wlg || prefetch Wr->B0
    cpW(1, 1);                                            // [g1]
    gemm3(accV, m0w, n0w, lid, bxh, bxl, wbh(0), wbl(0));
    __syncthreads();                                      // B0 reads done
    cpW(0, 2);                                            // [g1,g2]
    asm volatile("cp.async.wait_group 1;");               // g1 done: Wlg in B1
    __syncthreads();
    gemm3(accG, m0w, n0w, lid, bxh, bxl, wbh(1), wbl(1));
    combineFlush(g_left);                                 // (syncs inside; B1 reads done)

    // ---- right pair
    cpW(1, 3);                                            // [g2,g3]
    asm volatile("cp.async.wait_group 1;");               // g2 done: Wr in B0
    __syncthreads();
    gemm3(accV, m0w, n0w, lid, bxh, bxl, wbh(0), wbl(0));
    __syncthreads();                                      // B0 reads done
    cpW(0, 4);                                            // [g3,g4]
    asm volatile("cp.async.wait_group 1;");               // g3 done: Wrg in B1
    __syncthreads();
    gemm3(accG, m0w, n0w, lid, bxh, bxl, wbh(1), wbl(1));
    combineFlush(g_right);

    // ---- out_gate
    asm volatile("cp.async.wait_group 0;");               // g4 done: Wog in B0
    __syncthreads();
    gemm3(accV, m0w, n0w, lid, bxh, bxl, wbh(0), wbl(0));
    #pragma unroll
    for (int mt = 0; mt < 2; mt++) {
        int rA = m0w + mt * 16 + (lid >> 2);
        #pragma unroll
        for (int nt = 0; nt < 4; nt++) {
            int c = n0w + nt * 8 + 2 * (lid & 3);
            float2 o0 = make_float2(sigf(accV[mt][nt][0]), sigf(accV[mt][nt][1]));
            float2 o1 = make_float2(sigf(accV[mt][nt][2]), sigf(accV[mt][nt][3]));
            *(float2*)(g_outgate + (size_t)(pos0 + rA) * 128 + c)     = o0;
            *(float2*)(g_outgate + (size_t)(pos0 + rA + 8) * 128 + c) = o1;
        }
    }
}

// =====================================================================
// Kernel B: per-channel batched GEMM (unchanged — passing)
// =====================================================================
__device__ __forceinline__ uint32_t swOff(int row, int chunk) {
    return (uint32_t)(row * 64 + ((chunk ^ (row & 7)) << 3));
}

__global__ void __launch_bounds__(256) kernB()
{
    extern __shared__ __nv_bfloat16 smb[];
    const int tid = threadIdx.x;
    const int d  = blockIdx.z;
    const int i0 = blockIdx.y * 128;
    const int j0 = blockIdx.x * 128;
    const __nv_bfloat16* A = g_left  + (size_t)d * NN;
    const __nv_bfloat16* B = g_right + (size_t)d * NN;

    const int warp = tid >> 5, lane = tid & 31;
    const int m0 = (warp >> 2) * 64;
    const int n0 = (warp & 3) * 32;
    const uint32_t base = (uint32_t)__cvta_generic_to_shared(smb);

    float acc[4][4][4];
    #pragma unroll
    for (int mi = 0; mi < 4; mi++)
        #pragma unroll
        for (int ni = 0; ni < 4; ni++)
            #pragma unroll
            for (int e = 0; e < 4; e++) acc[mi][ni][e] = 0.f;

    const int aRow = ((lane & 8) ? 8 : 0) + (lane & 7);
    const int aChk = (lane >> 4);
    const int bRow = ((lane & 16) ? 8 : 0) + (lane & 7);
    const int bChk = ((lane >> 3) & 1);

    auto loadTile = [&](int st, int kb) {
        uint32_t sbase = base + (uint32_t)st * 32768;
        #pragma unroll
        for (int t = 0; t < 4; t++) {
            int idx = tid + t * 256;
            int r = idx >> 3, c = idx & 7;
            uint32_t so = swOff(r, c) * 2;
            cpa16(sbase + so,         A + (size_t)(i0 + r) * NDIM + kb + c * 8);
            cpa16(sbase + 16384 + so, B + (size_t)(j0 + r) * NDIM + kb + c * 8);
        }
        cpaCommit();
    };

    loadTile(0, 0);
    #pragma unroll 1
    for (int k = 0; k < 6; k++) {
        const int cur = k & 1;
        if (k < 5) loadTile(1 - cur, (k + 1) * 64);
        if (k < 5) asm volatile("cp.async.wait_group 1;");
        else       asm volatile("cp.async.wait_group 0;");
        __syncthreads();

        const uint32_t sA = base + (uint32_t)cur * 32768;
        const uint32_t sB = sA + 16384;
        #pragma unroll
        for (int kk = 0; kk < 64; kk += 16) {
            uint32_t af[4][4];
            #pragma unroll
            for (int mi = 0; mi < 4; mi++) {
                int row = m0 + mi * 16 + aRow;
                ldm4(af[mi], sA + swOff(row, (kk >> 3) + aChk) * 2);
            }
            uint32_t bf[2][4];
            #pragma unroll
            for (int p = 0; p < 2; p++) {
                int row = n0 + p * 16 + bRow;
                ldm4(bf[p], sB + swOff(row, (kk >> 3) + bChk) * 2);
            }
            #pragma unroll
            for (int mi = 0; mi < 4; mi++) {
                mma16816(acc[mi][0], af[mi], bf[0][0], bf[0][1]);
                mma16816(acc[mi][1], af[mi], bf[0][2], bf[0][3]);
                mma16816(acc[mi][2], af[mi], bf[1][0], bf[1][1]);
                mma16816(acc[mi][3], af[mi], bf[1][2], bf[1][3]);
            }
        }
        __syncthreads();
    }

    __nv_bfloat16* C = g_accbf + (size_t)d * NN;
    const int r = lane >> 2, cp = (lane & 3) * 2;
    #pragma unroll
    for (int mi = 0; mi < 4; mi++)
        #pragma unroll
        for (int ni = 0; ni < 4; ni++) {
            int gi = i0 + m0 + mi * 16 + r;
            int gj = j0 + n0 + ni * 8 + cp;
            *(__nv_bfloat162*)(C + (size_t)gi * NDIM + gj) =
                __floats2bfloat162_rn(acc[mi][ni][0], acc[mi][ni][1]);
            *(__nv_bfloat162*)(C + (size_t)(gi + 8) * NDIM + gj) =
                __floats2bfloat162_rn(acc[mi][ni][2], acc[mi][ni][3]);
        }
}

// =====================================================================
// Kernel C: out-LN + out_gate + @W_out^T via bf16x3 HMMA (unchanged)
// =====================================================================
struct SmemC2 {
    __nv_bfloat16 xh[64 * 128];
    __nv_bfloat16 xl[64 * 128];
    union {
        float s[64][132];
        __nv_bfloat16 wh[128 * 128];
    };
    __nv_bfloat16 wl[128 * 128];
    float onw[128];
    float onb[128];
};

__device__ __forceinline__ void stageW4(__nv_bfloat16* wh, __nv_bfloat16* wl,
                                        const float* __restrict__ W, int tid) {
    #pragma unroll
    for (int t = 0; t < 16; t++) {
        int idx = tid + t * 256;
        int h = idx >> 5, kq = idx & 31;
        float4 w = *(const float4*)(W + h * 128 + kq * 4);
        __nv_bfloat162 h01 = __floats2bfloat162_rn(w.x, w.y);
        __nv_bfloat162 h23 = __floats2bfloat162_rn(w.z, w.w);
        __nv_bfloat162 l01 = __floats2bfloat162_rn(w.x - __bfloat162float(h01.x),
                                                   w.y - __bfloat162float(h01.y));
        __nv_bfloat162 l23 = __floats2bfloat162_rn(w.z - __bfloat162float(h23.x),
                                                   w.w - __bfloat162float(h23.y));
        uint32_t off = sw128(h, kq >> 1) + ((kq & 1) << 2);
        *(__nv_bfloat162*)(wh + off)     = h01;
        *(__nv_bfloat162*)(wh + off + 2) = h23;
        *(__nv_bfloat162*)(wl + off)     = l01;
        *(__nv_bfloat162*)(wl + off + 2) = l23;
    }
}

__global__ void __launch_bounds__(256, 2)
kernC(const float* __restrict__ onw, const float* __restrict__ onb,
      const float* __restrict__ Wout, float* __restrict__ out)
{
    extern __shared__ char raw[];
    SmemC2& sm = *reinterpret_cast<SmemC2*>(raw);
    const int tid = threadIdx.x;
    const int pos0 = blockIdx.x * 64;
    const int wid = tid >> 5, lid = tid & 31;

    if (tid < 128) { sm.onw[tid] = onw[tid]; sm.onb[tid] = onb[tid]; }
    #pragma unroll
    for (int t = 0; t < 32; t++) {
        int idx = tid + t * 256;
        int dch = idx >> 6, p = idx & 63;
        sm.s[p][dch] = __bfloat162float(g_accbf[(size_t)dch * NN + pos0 + p]);
    }
    __syncthreads();

    #pragma unroll
    for (int rr = 0; rr < 8; rr++) {
        int p = wid * 8 + rr;
        float4 v = *(const float4*)&sm.s[p][lid * 4];
        float ssum = v.x + v.y + v.z + v.w;
        float q = v.x * v.x + v.y * v.y + v.z * v.z + v.w * v.w;
        #pragma unroll
        for (int o = 16; o; o >>= 1) {
            ssum += __shfl_xor_sync(0xffffffffu, ssum, o);
            q    += __shfl_xor_sync(0xffffffffu, q, o);
        }
        float mu = ssum * (1.f / 128.f);
        float rstd = rsqrtf(q * (1.f / 128.f) - mu * mu + 1e-5f);
        float4 wv = *(const float4*)&sm.onw[lid * 4];
        float4 bv = *(const float4*)&sm.onb[lid * 4];
        float4 og = *(const float4*)(g_outgate + (size_t)(pos0 + p) * 128 + lid * 4);
        float y0 = ((v.x - mu) * rstd * wv.x + bv.x) * og.x;
        float y1 = ((v.y - mu) * rstd * wv.y + bv.y) * og.y;
        float y2 = ((v.z - mu) * rstd * wv.z + bv.z) * og.z;
        float y3 = ((v.w - mu) * rstd * wv.w + bv.w) * og.w;
        __nv_bfloat162 h01 = __floats2bfloat162_rn(y0, y1);
        __nv_bfloat162 h23 = __floats2bfloat162_rn(y2, y3);
        __nv_bfloat162 l01 = __floats2bfloat162_rn(y0 - __bfloat162float(h01.x),
                                                   y1 - __bfloat162float(h01.y));
        __nv_bfloat162 l23 = __floats2bfloat162_rn(y2 - __bfloat162float(h23.x),
                                                   y3 - __bfloat162float(h23.y));
        uint32_t off = sw128(p, lid >> 1) + ((lid & 1) << 2);
        *(__nv_bfloat162*)(sm.xh + off)     = h01;
        *(__nv_bfloat162*)(sm.xh + off + 2) = h23;
        *(__nv_bfloat162*)(sm.xl + off)     = l01;
        *(__nv_bfloat162*)(sm.xl + off + 2) = l23;
    }
    __syncthreads();

    stageW4(sm.wh, sm.wl, Wout, tid);
    __syncthreads();

    const int m0w = (wid >> 2) * 32;
    const int n0w = (wid & 3) * 32;
    const uint32_t bxh = (uint32_t)__cvta_generic_to_shared(sm.xh);
    const uint32_t bxl = (uint32_t)__cvta_generic_to_shared(sm.xl);
    const uint32_t bwh = (uint32_t)__cvta_generic_to_shared(sm.wh);
    const uint32_t bwl = (uint32_t)__cvta_generic_to_shared(sm.wl);
    float acc[2][4][4];
    gemm3(acc, m0w, n0w, lid, bxh, bxl, bwh, bwl);

    #pragma unroll
    for (int mt = 0; mt < 2; mt++) {
        int rA = m0w + mt * 16 + (lid >> 2);
        #pragma unroll
        for (int nt = 0; nt < 4; nt++) {
            int c = n0w + nt * 8 + 2 * (lid & 3);
            *(float2*)(out + (size_t)(pos0 + rA) * 128 + c) =
                make_float2(acc[mt][nt][0], acc[mt][nt][1]);
            *(float2*)(out + (size_t)(pos0 + rA + 8) * 128 + c) =
                make_float2(acc[mt][nt][2], acc[mt][nt][3]);
        }
    }
}

// =====================================================================
extern "C" void kernel_launch(void* const* d_in, const int* in_sizes, int n_in,
                              void* d_out, int out_size)
{
    (void)in_sizes; (void)n_in; (void)out_size;
    const float* x    = (const float*)d_in[0];
    const float* mask = (const float*)d_in[1];
    const float* nw   = (const float*)d_in[2];
    const float* nb   = (const float*)d_in[3];
    const float* Wl   = (const float*)d_in[4];
    const float* Wr   = (const float*)d_in[5];
    const float* Wlg  = (const float*)d_in[6];
    const float* Wrg  = (const float*)d_in[7];
    const float* Wog  = (const float*)d_in[8];
    const float* onw  = (const float*)d_in[9];
    const float* onb  = (const float*)d_in[10];
    const float* Wout = (const float*)d_in[11];
    float* out = (float*)d_out;

    cudaFuncSetAttribute(kernA, cudaFuncAttributeMaxDynamicSharedMemorySize, (int)sizeof(SmemA5));
    cudaFuncSetAttribute(kernB, cudaFuncAttributeMaxDynamicSharedMemorySize, 65536);
    cudaFuncSetAttribute(kernC, cudaFuncAttributeMaxDynamicSharedMemorySize, (int)sizeof(SmemC2));

    kernW<<<5, 256>>>(Wl, Wlg, Wr, Wrg, Wog);
    kernA<<<NN / 128, 512, sizeof(SmemA5)>>>(x, mask, nw, nb);
    kernB<<<dim3(3, 3, 128), 256, 65536>>>();
    kernC<<<NN / 64, 256, sizeof(SmemC2)>>>(onw, onb, Wout, out);
}